// round 5
// baseline (speedup 1.0000x reference)
#include <cuda_runtime.h>
#include <cuda_bf16.h>
#include <math.h>
#include <stdint.h>

// ---------------------------------------------------------------------------
// HawkBlock: mma.sync bf16 split-3 GEMMs, 16-warp CTAs (32x32 warp tiles),
// 3-stage cp.async pipeline + parallel scan.
// ---------------------------------------------------------------------------

#define NTOK   16384
#define HIDDEN 1024
#define DREC   2048
#define INTER  4096
#define TLEN   4096
#define NB     4

#define SCHUNK   64
#define NCHUNKS  (TLEN / SCHUNK)   // 64
#define NCHAN    (NB * DREC)       // 8192

typedef __nv_bfloat16  bf16;
typedef __nv_bfloat162 bf162;

// ---- static scratch: activations ----
__device__ bf16  g_h_hi  [(size_t)NTOK * HIDDEN];
__device__ bf16  g_h_lo  [(size_t)NTOK * HIDDEN];
__device__ bf16  g_h2_hi [(size_t)NTOK * HIDDEN];
__device__ bf16  g_h2_lo [(size_t)NTOK * HIDDEN];
__device__ float g_xres  [(size_t)NTOK * HIDDEN];
__device__ bf16  g_xin_hi[(size_t)NTOK * DREC];
__device__ bf16  g_xin_lo[(size_t)NTOK * DREC];
__device__ float g_gate  [(size_t)NTOK * DREC];
__device__ float g_a     [(size_t)NTOK * DREC];
__device__ float g_hp    [(size_t)NTOK * DREC];
__device__ float g_P     [(size_t)NTOK * DREC];
__device__ bf16  g_y_hi  [(size_t)NTOK * DREC];
__device__ bf16  g_y_lo  [(size_t)NTOK * DREC];
__device__ float g_mg    [(size_t)NTOK * INTER];
__device__ bf16  g_mu_hi [(size_t)NTOK * INTER];
__device__ bf16  g_mu_lo [(size_t)NTOK * INTER];
__device__ float g_csum  [2 * NCHUNKS * NCHAN];
__device__ float g_carry [NCHUNKS * NCHAN];

// ---- static scratch: split weights (hi/lo bf16) ----
__device__ bf16 g_wi_hi [(size_t)DREC * HIDDEN],  g_wi_lo [(size_t)DREC * HIDDEN];
__device__ bf16 g_wg_hi [(size_t)DREC * HIDDEN],  g_wg_lo [(size_t)DREC * HIDDEN];
__device__ bf16 g_wa_hi [(size_t)DREC * DREC],    g_wa_lo [(size_t)DREC * DREC];
__device__ bf16 g_wo_hi [(size_t)HIDDEN * DREC],  g_wo_lo [(size_t)HIDDEN * DREC];
__device__ bf16 g_wmg_hi[(size_t)INTER * HIDDEN], g_wmg_lo[(size_t)INTER * HIDDEN];
__device__ bf16 g_wmu_hi[(size_t)INTER * HIDDEN], g_wmu_lo[(size_t)INTER * HIDDEN];
__device__ bf16 g_wmd_hi[(size_t)HIDDEN * INTER], g_wmd_lo[(size_t)HIDDEN * INTER];

// ---------------------------------------------------------------------------
// helpers
// ---------------------------------------------------------------------------
__device__ __forceinline__ uint32_t smem_u32(const void* p) {
    uint32_t a;
    asm("{ .reg .u64 t; cvta.to.shared.u64 t, %1; cvt.u32.u64 %0, t; }"
        : "=r"(a) : "l"(p));
    return a;
}
__device__ __forceinline__ void cp16(uint32_t dst, const void* src) {
    asm volatile("cp.async.cg.shared.global [%0], [%1], 16;"
                 :: "r"(dst), "l"(src));
}
__device__ __forceinline__ void cp_commit() {
    asm volatile("cp.async.commit_group;" ::: "memory");
}
template<int N>
__device__ __forceinline__ void cp_wait() {
    asm volatile("cp.async.wait_group %0;" :: "n"(N) : "memory");
}
__device__ __forceinline__ void ldsm4(uint32_t (&r)[4], uint32_t addr) {
    asm volatile("ldmatrix.sync.aligned.m8n8.x4.shared.b16 {%0,%1,%2,%3}, [%4];"
                 : "=r"(r[0]), "=r"(r[1]), "=r"(r[2]), "=r"(r[3]) : "r"(addr));
}
__device__ __forceinline__ void mma_bf16(float (&d)[4], const uint32_t (&a)[4],
                                         uint32_t b0, uint32_t b1) {
    asm volatile("mma.sync.aligned.m16n8k16.row.col.f32.bf16.bf16.f32 "
                 "{%0,%1,%2,%3}, {%4,%5,%6,%7}, {%8,%9}, {%0,%1,%2,%3};"
                 : "+f"(d[0]), "+f"(d[1]), "+f"(d[2]), "+f"(d[3])
                 : "r"(a[0]), "r"(a[1]), "r"(a[2]), "r"(a[3]), "r"(b0), "r"(b1));
}
__device__ __forceinline__ uint32_t pack_bf2(bf16 a, bf16 b) {
    bf162 t = __halves2bfloat162(a, b);
    return *reinterpret_cast<uint32_t*>(&t);
}
__device__ __forceinline__ void split1(float v, bf16& h, bf16& l) {
    h = __float2bfloat16(v);
    l = __float2bfloat16(v - __bfloat162float(h));
}

// ---------------------------------------------------------------------------
// batched weight split: up to 4 arrays per launch (sizes in float4 units)
// ---------------------------------------------------------------------------
__global__ __launch_bounds__(256) void split_multi(
    const float* __restrict__ s0, bf16* __restrict__ h0, bf16* __restrict__ l0, int n0,
    const float* __restrict__ s1, bf16* __restrict__ h1, bf16* __restrict__ l1, int n1,
    const float* __restrict__ s2, bf16* __restrict__ h2, bf16* __restrict__ l2, int n2,
    const float* __restrict__ s3, bf16* __restrict__ h3, bf16* __restrict__ l3, int n3)
{
    int i = blockIdx.x * 256 + threadIdx.x;
    const float* s; bf16 *hh, *ll; int j = i;
    if (j < n0) { s = s0; hh = h0; ll = l0; }
    else {
        j -= n0;
        if (j < n1) { s = s1; hh = h1; ll = l1; }
        else {
            j -= n1;
            if (j < n2) { s = s2; hh = h2; ll = l2; }
            else {
                j -= n2;
                if (j >= n3) return;
                s = s3; hh = h3; ll = l3;
            }
        }
    }
    float4 v = reinterpret_cast<const float4*>(s)[j];
    bf16 a0, a1, a2, a3, b0, b1, b2, b3;
    split1(v.x, a0, b0); split1(v.y, a1, b1);
    split1(v.z, a2, b2); split1(v.w, a3, b3);
    reinterpret_cast<uint2*>(hh)[j] = make_uint2(pack_bf2(a0, a1), pack_bf2(a2, a3));
    reinterpret_cast<uint2*>(ll)[j] = make_uint2(pack_bf2(b0, b1), pack_bf2(b2, b3));
}

// ---------------------------------------------------------------------------
// RMSNorm -> hi/lo bf16 planes
// ---------------------------------------------------------------------------
__global__ __launch_bounds__(256) void rmsnorm_split(
    const float* __restrict__ x, const float* __restrict__ w,
    bf16* __restrict__ oh, bf16* __restrict__ ol)
{
    int tkn = blockIdx.x;
    int t = threadIdx.x;
    float4 v = reinterpret_cast<const float4*>(x + (size_t)tkn * HIDDEN)[t];
    float s = v.x * v.x + v.y * v.y + v.z * v.z + v.w * v.w;
    #pragma unroll
    for (int o = 16; o > 0; o >>= 1) s += __shfl_xor_sync(0xFFFFFFFFu, s, o);
    __shared__ float ws[8];
    __shared__ float tot_sh;
    if ((t & 31) == 0) ws[t >> 5] = s;
    __syncthreads();
    if (t < 32) {
        float z = (t < 8) ? ws[t] : 0.0f;
        #pragma unroll
        for (int o = 4; o > 0; o >>= 1) z += __shfl_xor_sync(0xFFFFFFFFu, z, o);
        if (t == 0) tot_sh = z;
    }
    __syncthreads();
    float r = rsqrtf(tot_sh * (1.0f / HIDDEN) + 1e-6f);
    float4 wv = reinterpret_cast<const float4*>(w)[t];
    float f0 = v.x * r * wv.x, f1 = v.y * r * wv.y;
    float f2 = v.z * r * wv.z, f3 = v.w * r * wv.w;
    bf16 h0, h1, h2, h3, l0, l1, l2, l3;
    split1(f0, h0, l0); split1(f1, h1, l1);
    split1(f2, h2, l2); split1(f3, h3, l3);
    size_t q = (size_t)tkn * (HIDDEN / 4) + t;
    reinterpret_cast<uint2*>(oh)[q] = make_uint2(pack_bf2(h0, h1), pack_bf2(h2, h3));
    reinterpret_cast<uint2*>(ol)[q] = make_uint2(pack_bf2(l0, l1), pack_bf2(l2, l3));
}

// ---------------------------------------------------------------------------
// GEMM: C[N=16384, M] = A[N,K] @ W[M,K]^T, bf16 split-3, fp32 accum.
// CTA 128x128, BK=64, 512 threads / 16 warps (warp tile 32x32, 4x4 grid).
// 3-buffer smem (64KB each: Ah,Al,Bh,Bl 16KB), cp.async depth 2,
// one __syncthreads per chunk. Fused inner loop (hh/hl/lh per k-step).
// ---------------------------------------------------------------------------
#define EPI_NONE          0
#define EPI_SIGMOID       1
#define EPI_BIAS_SIGMOID  2
#define EPI_RESADD        3
#define EPI_SILU_AUX_MUL  4

template<int EPI>
__device__ __forceinline__ float epi_apply(float v, const float* __restrict__ aux,
                                           size_t idx, int col)
{
    if (EPI == EPI_SIGMOID)      return 1.0f / (1.0f + expf(-v));
    if (EPI == EPI_BIAS_SIGMOID) { float z = v + __ldg(&aux[col]);
                                   return 1.0f / (1.0f + expf(-z)); }
    if (EPI == EPI_RESADD)       return v + __ldg(&aux[idx]);
    if (EPI == EPI_SILU_AUX_MUL) { float g = __ldg(&aux[idx]);
                                   return v * (g / (1.0f + expf(-g))); }
    return v;
}

#define STAGE_B   65536u
#define GEMM_SMEM (3 * 65536)

template<int EPI, bool SPLIT>
__global__ __launch_bounds__(512, 1) void mma_gemm(
    const bf16* __restrict__ Ah, const bf16* __restrict__ Al,
    const bf16* __restrict__ Bh, const bf16* __restrict__ Bl,
    float* __restrict__ Cf, bf16* __restrict__ Ch, bf16* __restrict__ Cl,
    const float* __restrict__ aux, int M, int K)
{
    extern __shared__ char smem[];
    const uint32_t sb = smem_u32(smem);
    const int tid = threadIdx.x;
    const int lane = tid & 31;
    const int wid = tid >> 5;
    const int warp_m = wid >> 2;    // 0..3
    const int warp_n = wid & 3;     // 0..3
    const int rowBlock = blockIdx.y * 128;
    const int colBlock = blockIdx.x * 128;
    const int nch = K >> 6;

    const bf16* gp0 = Ah + (size_t)rowBlock * K;
    const bf16* gp1 = Al + (size_t)rowBlock * K;
    const bf16* gp2 = Bh + (size_t)colBlock * K;
    const bf16* gp3 = Bl + (size_t)colBlock * K;

    auto issue = [&](int buf, int c) {
        const int kb = c * 64;
        uint32_t st = sb + (uint32_t)buf * STAGE_B;
        #pragma unroll
        for (int arr = 0; arr < 4; arr++) {
            const bf16* g = (arr == 0) ? gp0 : (arr == 1) ? gp1 : (arr == 2) ? gp2 : gp3;
            uint32_t db = st + arr * 16384u;
            #pragma unroll
            for (int i = 0; i < 2; i++) {
                int u = tid + i * 512;
                int r = u >> 3, cc = u & 7;
                cp16(db + r * 128 + ((cc ^ (r & 7)) << 4),
                     g + (size_t)r * K + kb + cc * 8);
            }
        }
        cp_commit();
    };

    float acc[2][4][4];
    #pragma unroll
    for (int i = 0; i < 2; i++)
        #pragma unroll
        for (int j = 0; j < 4; j++)
            #pragma unroll
            for (int k = 0; k < 4; k++) acc[i][j][k] = 0.0f;

    issue(0, 0);
    if (nch > 1) issue(1, 1);

    // lane-level ldmatrix addressing (row&7 == lane&7 for both A and B)
    const int aRow0 = warp_m * 32 + (lane & 7) + ((lane >> 3) & 1) * 8;
    const int aKh   = (lane >> 4) & 1;
    const int bRow0 = warp_n * 32 + ((lane >> 4) & 1) * 8 + (lane & 7);
    const int bKh   = (lane >> 3) & 1;
    const int swz   = lane & 7;

    for (int c = 0; c < nch; c++) {
        int buf = c % 3;
        if (c + 1 < nch) cp_wait<1>(); else cp_wait<0>();
        __syncthreads();
        // refill the buffer freed by chunk c-1 (== buffer (c+2)%3)
        if (c + 2 < nch) issue((c + 2) % 3, c + 2);

        uint32_t st = sb + (uint32_t)buf * STAGE_B;
        #pragma unroll
        for (int ks = 0; ks < 4; ks++) {
            uint32_t ah[2][4], al[2][4];
            #pragma unroll
            for (int mt = 0; mt < 2; mt++) {
                uint32_t roff = (uint32_t)(aRow0 + mt * 16) * 128
                              + (uint32_t)(((ks * 2 + aKh) ^ swz) << 4);
                ldsm4(ah[mt], st + roff);
                ldsm4(al[mt], st + 16384u + roff);
            }
            uint32_t bh[4][2], bl[4][2];
            #pragma unroll
            for (int p = 0; p < 2; p++) {
                uint32_t roff = (uint32_t)(bRow0 + p * 16) * 128
                              + (uint32_t)(((ks * 2 + bKh) ^ swz) << 4);
                uint32_t t4[4];
                ldsm4(t4, st + 32768u + roff);
                bh[2 * p][0] = t4[0]; bh[2 * p][1] = t4[1];
                bh[2 * p + 1][0] = t4[2]; bh[2 * p + 1][1] = t4[3];
                ldsm4(t4, st + 49152u + roff);
                bl[2 * p][0] = t4[0]; bl[2 * p][1] = t4[1];
                bl[2 * p + 1][0] = t4[2]; bl[2 * p + 1][1] = t4[3];
            }
            // hh
            #pragma unroll
            for (int mt = 0; mt < 2; mt++)
                #pragma unroll
                for (int nt = 0; nt < 4; nt++)
                    mma_bf16(acc[mt][nt], ah[mt], bh[nt][0], bh[nt][1]);
            // hl
            #pragma unroll
            for (int mt = 0; mt < 2; mt++)
                #pragma unroll
                for (int nt = 0; nt < 4; nt++)
                    mma_bf16(acc[mt][nt], ah[mt], bl[nt][0], bl[nt][1]);
            // lh
            #pragma unroll
            for (int mt = 0; mt < 2; mt++)
                #pragma unroll
                for (int nt = 0; nt < 4; nt++)
                    mma_bf16(acc[mt][nt], al[mt], bh[nt][0], bh[nt][1]);
        }
        __syncthreads();
    }

    // epilogue
    #pragma unroll
    for (int mt = 0; mt < 2; mt++) {
        #pragma unroll
        for (int nt = 0; nt < 4; nt++) {
            int col = colBlock + warp_n * 32 + nt * 8 + (lane & 3) * 2;
            #pragma unroll
            for (int half = 0; half < 2; half++) {
                int row = rowBlock + warp_m * 32 + mt * 16 + (lane >> 2) + half * 8;
                size_t idx = (size_t)row * M + col;
                float f0 = epi_apply<EPI>(acc[mt][nt][half * 2 + 0], aux, idx, col);
                float f1 = epi_apply<EPI>(acc[mt][nt][half * 2 + 1], aux, idx + 1, col + 1);
                if (SPLIT) {
                    bf16 h0, h1, l0, l1;
                    split1(f0, h0, l0); split1(f1, h1, l1);
                    *reinterpret_cast<uint32_t*>(Ch + idx) = pack_bf2(h0, h1);
                    *reinterpret_cast<uint32_t*>(Cl + idx) = pack_bf2(l0, l1);
                } else {
                    *reinterpret_cast<float2*>(Cf + idx) = make_float2(f0, f1);
                }
            }
        }
    }
}

// ---------------------------------------------------------------------------
// Parallel Hawk scan (3 passes)
// ---------------------------------------------------------------------------
__global__ __launch_bounds__(256) void scan_part1(
    const bf16* __restrict__ xh, const bf16* __restrict__ xl,
    const float* __restrict__ a,
    float* __restrict__ hp, float* __restrict__ P, float* __restrict__ csum)
{
    int id = blockIdx.x * 256 + threadIdx.x;
    int chunk = id >> 13;
    int chp = id & (NCHAN - 1);
    int b = chp >> 11;
    int d = chp & (DREC - 1);
    size_t base = ((size_t)b * TLEN + (size_t)chunk * SCHUNK) * DREC + d;

    float h = 0.0f, Aacc = 1.0f;
    #pragma unroll 4
    for (int t = 0; t < SCHUNK; t++) {
        size_t idx = base + (size_t)t * DREC;
        float at = __ldg(&a[idx]);
        float xt = __bfloat162float(__ldg(&xh[idx])) + __bfloat162float(__ldg(&xl[idx]));
        float s = sqrtf(fmaf(-at, at, 1.0f) + 1e-8f);
        h = fmaf(at, h, s * xt);
        Aacc *= at;
        hp[idx] = h;
        P[idx] = Aacc;
    }
    csum[(size_t)chunk * NCHAN + chp] = Aacc;
    csum[(size_t)NCHUNKS * NCHAN + (size_t)chunk * NCHAN + chp] = h;
}

__global__ __launch_bounds__(256) void scan_part2(
    const float* __restrict__ csum, float* __restrict__ carry)
{
    int chp = blockIdx.x * 256 + threadIdx.x;
    float h = 0.0f;
    #pragma unroll 8
    for (int c = 0; c < NCHUNKS; c++) {
        carry[(size_t)c * NCHAN + chp] = h;
        float Ac = csum[(size_t)c * NCHAN + chp];
        float hc = csum[(size_t)NCHUNKS * NCHAN + (size_t)c * NCHAN + chp];
        h = fmaf(Ac, h, hc);
    }
}

__global__ __launch_bounds__(256) void scan_part3(
    const float* __restrict__ hp, const float* __restrict__ P,
    const float* __restrict__ gate, const float* __restrict__ carry,
    bf16* __restrict__ yh, bf16* __restrict__ yl)
{
    size_t q = (size_t)blockIdx.x * 256 + threadIdx.x;  // float4 index
    size_t i = q * 4;
    size_t n = i >> 11;
    int d = (int)(i & (DREC - 1));
    int b = (int)(n >> 12);
    int t = (int)(n & (TLEN - 1));
    int c = t >> 6;

    float4 h4 = reinterpret_cast<const float4*>(hp)[q];
    float4 p4 = reinterpret_cast<const float4*>(P)[q];
    float4 g4 = reinterpret_cast<const float4*>(gate)[q];
    float4 cv = *reinterpret_cast<const float4*>(carry + (size_t)c * NCHAN + b * DREC + d);
    float o0 = g4.x * fmaf(p4.x, cv.x, h4.x);
    float o1 = g4.y * fmaf(p4.y, cv.y, h4.y);
    float o2 = g4.z * fmaf(p4.z, cv.z, h4.z);
    float o3 = g4.w * fmaf(p4.w, cv.w, h4.w);
    bf16 h0, h1, h2, h3, l0, l1, l2, l3;
    split1(o0, h0, l0); split1(o1, h1, l1);
    split1(o2, h2, l2); split1(o3, h3, l3);
    reinterpret_cast<uint2*>(yh)[q] = make_uint2(pack_bf2(h0, h1), pack_bf2(h2, h3));
    reinterpret_cast<uint2*>(yl)[q] = make_uint2(pack_bf2(l0, l1), pack_bf2(l2, l3));
}

// ---------------------------------------------------------------------------
// Launch
// ---------------------------------------------------------------------------
#define SYM(p, s) cudaGetSymbolAddress((void**)&p, s)

extern "C" void kernel_launch(void* const* d_in, const int* in_sizes, int n_in,
                              void* d_out, int out_size)
{
    const float* x       = (const float*)d_in[0];
    const float* ln1_w   = (const float*)d_in[1];
    const float* ln2_w   = (const float*)d_in[2];
    const float* w_in    = (const float*)d_in[3];
    const float* w_gate  = (const float*)d_in[4];
    const float* a_param = (const float*)d_in[5];
    const float* w_a     = (const float*)d_in[6];
    const float* w_out   = (const float*)d_in[7];
    const float* w_mg    = (const float*)d_in[8];
    const float* w_mu    = (const float*)d_in[9];
    const float* w_md    = (const float*)d_in[10];
    float* out = (float*)d_out;

    bf16 *hh, *hl, *h2h, *h2l, *xinh, *xinl, *yh, *yl, *muh, *mul;
    float *xres, *gate, *aa, *hp, *P, *mg, *csum, *carry;
    bf16 *wih, *wil, *wgh, *wgl, *wah, *wal, *woh, *wol;
    bf16 *wmgh, *wmgl, *wmuh, *wmul, *wmdh, *wmdl;

    SYM(hh, g_h_hi);   SYM(hl, g_h_lo);
    SYM(h2h, g_h2_hi); SYM(h2l, g_h2_lo);
    SYM(xinh, g_xin_hi); SYM(xinl, g_xin_lo);
    SYM(yh, g_y_hi);   SYM(yl, g_y_lo);
    SYM(muh, g_mu_hi); SYM(mul, g_mu_lo);
    SYM(xres, g_xres); SYM(gate, g_gate); SYM(aa, g_a);
    SYM(hp, g_hp);     SYM(P, g_P);       SYM(mg, g_mg);
    SYM(csum, g_csum); SYM(carry, g_carry);
    SYM(wih, g_wi_hi);  SYM(wil, g_wi_lo);
    SYM(wgh, g_wg_hi);  SYM(wgl, g_wg_lo);
    SYM(wah, g_wa_hi);  SYM(wal, g_wa_lo);
    SYM(woh, g_wo_hi);  SYM(wol, g_wo_lo);
    SYM(wmgh, g_wmg_hi); SYM(wmgl, g_wmg_lo);
    SYM(wmuh, g_wmu_hi); SYM(wmul, g_wmu_lo);
    SYM(wmdh, g_wmd_hi); SYM(wmdl, g_wmd_lo);

    cudaFuncSetAttribute(mma_gemm<EPI_NONE, true>,          cudaFuncAttributeMaxDynamicSharedMemorySize, GEMM_SMEM);
    cudaFuncSetAttribute(mma_gemm<EPI_NONE, false>,         cudaFuncAttributeMaxDynamicSharedMemorySize, GEMM_SMEM);
    cudaFuncSetAttribute(mma_gemm<EPI_SIGMOID, false>,      cudaFuncAttributeMaxDynamicSharedMemorySize, GEMM_SMEM);
    cudaFuncSetAttribute(mma_gemm<EPI_BIAS_SIGMOID, false>, cudaFuncAttributeMaxDynamicSharedMemorySize, GEMM_SMEM);
    cudaFuncSetAttribute(mma_gemm<EPI_RESADD, false>,       cudaFuncAttributeMaxDynamicSharedMemorySize, GEMM_SMEM);
    cudaFuncSetAttribute(mma_gemm<EPI_SILU_AUX_MUL, true>,  cudaFuncAttributeMaxDynamicSharedMemorySize, GEMM_SMEM);

    dim3 blk(256);
    dim3 gblk(512);
    const int GY = NTOK / 128;   // 128

    const int n_ih = DREC * HIDDEN / 4;   // 524288
    const int n_aa = DREC * DREC / 4;     // 1048576
    const int n_mh = INTER * HIDDEN / 4;  // 1048576

    // launch 0: split w_in, w_gate, w_a
    split_multi<<<(n_ih + n_ih + n_aa + 255) / 256, blk>>>(
        w_in, wih, wil, n_ih,
        w_gate, wgh, wgl, n_ih,
        w_a, wah, wal, n_aa,
        w_a, wah, wal, 0);
    // launch 1: split w_out, w_mg, w_mu, w_md
    split_multi<<<(n_ih + 3 * n_mh + 255) / 256, blk>>>(
        w_out, woh, wol, n_ih,
        w_mg, wmgh, wmgl, n_mh,
        w_mu, wmuh, wmul, n_mh,
        w_md, wmdh, wmdl, n_mh);

    // launch 2: h = rmsnorm(x, ln1)
    rmsnorm_split<<<NTOK, blk>>>(x, ln1_w, hh, hl);

    // launch 3: xin = h @ w_in^T
    mma_gemm<EPI_NONE, true><<<dim3(DREC / 128, GY), gblk, GEMM_SMEM>>>(
        hh, hl, wih, wil, nullptr, xinh, xinl, nullptr, DREC, HIDDEN);

    // launch 4: gate = sigmoid(h @ w_gate^T)
    mma_gemm<EPI_SIGMOID, false><<<dim3(DREC / 128, GY), gblk, GEMM_SMEM>>>(
        hh, hl, wgh, wgl, gate, nullptr, nullptr, nullptr, DREC, HIDDEN);

    // launch 5 (ncu -s 5 -c 1 profiles this): a = sigmoid(a_param + xin @ w_a^T)
    mma_gemm<EPI_BIAS_SIGMOID, false><<<dim3(DREC / 128, GY), gblk, GEMM_SMEM>>>(
        xinh, xinl, wah, wal, aa, nullptr, nullptr, a_param, DREC, DREC);

    // scan
    scan_part1<<<(NCHUNKS * NCHAN) / 256, blk>>>(xinh, xinl, aa, hp, P, csum);
    scan_part2<<<NCHAN / 256, blk>>>(csum, carry);
    scan_part3<<<(int)((size_t)NTOK * DREC / 4 / 256), blk>>>(hp, P, gate, carry, yh, yl);

    // xres = x + y @ w_out^T
    mma_gemm<EPI_RESADD, false><<<dim3(HIDDEN / 128, GY), gblk, GEMM_SMEM>>>(
        yh, yl, woh, wol, xres, nullptr, nullptr, x, HIDDEN, DREC);

    // h2 = rmsnorm(xres, ln2)
    rmsnorm_split<<<NTOK, blk>>>(xres, ln2_w, h2h, h2l);

    // mg = h2 @ w_mlp_gate^T
    mma_gemm<EPI_NONE, false><<<dim3(INTER / 128, GY), gblk, GEMM_SMEM>>>(
        h2h, h2l, wmgh, wmgl, mg, nullptr, nullptr, nullptr, INTER, HIDDEN);

    // mu = silu(mg) * (h2 @ w_mlp_up^T)
    mma_gemm<EPI_SILU_AUX_MUL, true><<<dim3(INTER / 128, GY), gblk, GEMM_SMEM>>>(
        h2h, h2l, wmuh, wmul, nullptr, muh, mul, mg, INTER, HIDDEN);

    // out = xres + mu @ w_mlp_down^T
    mma_gemm<EPI_RESADD, false><<<dim3(HIDDEN / 128, GY), gblk, GEMM_SMEM>>>(
        muh, mul, wmdh, wmdl, out, nullptr, nullptr, xres, HIDDEN, INTER);
}

// round 6
// speedup vs baseline: 2.1517x; 2.1517x over previous
#include <cuda_runtime.h>
#include <cuda_fp16.h>
#include <math.h>
#include <stdint.h>

// ---------------------------------------------------------------------------
// HawkBlock: single-product fp16 mma.sync GEMMs (CTA 128x256, 64x64 warp
// tiles, 4-stage cp.async) + parallel scan.
// ---------------------------------------------------------------------------

#define NTOK   16384
#define HIDDEN 1024
#define DREC   2048
#define INTER  4096
#define TLEN   4096
#define NB     4

#define SCHUNK   64
#define NCHUNKS  (TLEN / SCHUNK)   // 64
#define NCHAN    (NB * DREC)       // 8192

typedef __half  f16;

// ---- static scratch: activations ----
__device__ f16   g_h   [(size_t)NTOK * HIDDEN];
__device__ f16   g_h2  [(size_t)NTOK * HIDDEN];
__device__ float g_xres[(size_t)NTOK * HIDDEN];
__device__ f16   g_xin [(size_t)NTOK * DREC];
__device__ float g_gate[(size_t)NTOK * DREC];
__device__ float g_a   [(size_t)NTOK * DREC];
__device__ float g_hp  [(size_t)NTOK * DREC];
__device__ float g_P   [(size_t)NTOK * DREC];
__device__ f16   g_y   [(size_t)NTOK * DREC];
__device__ float g_mg  [(size_t)NTOK * INTER];
__device__ f16   g_mu  [(size_t)NTOK * INTER];
__device__ float g_csum [2 * NCHUNKS * NCHAN];
__device__ float g_carry[NCHUNKS * NCHAN];

// ---- static scratch: fp16 weights ----
__device__ f16 g_wi [(size_t)DREC * HIDDEN];
__device__ f16 g_wg [(size_t)DREC * HIDDEN];
__device__ f16 g_wa [(size_t)DREC * DREC];
__device__ f16 g_wo [(size_t)HIDDEN * DREC];
__device__ f16 g_wmg[(size_t)INTER * HIDDEN];
__device__ f16 g_wmu[(size_t)INTER * HIDDEN];
__device__ f16 g_wmd[(size_t)HIDDEN * INTER];

// ---------------------------------------------------------------------------
// helpers
// ---------------------------------------------------------------------------
__device__ __forceinline__ uint32_t smem_u32(const void* p) {
    uint32_t a;
    asm("{ .reg .u64 t; cvta.to.shared.u64 t, %1; cvt.u32.u64 %0, t; }"
        : "=r"(a) : "l"(p));
    return a;
}
__device__ __forceinline__ void cp16(uint32_t dst, const void* src) {
    asm volatile("cp.async.cg.shared.global [%0], [%1], 16;"
                 :: "r"(dst), "l"(src));
}
__device__ __forceinline__ void cp_commit() {
    asm volatile("cp.async.commit_group;" ::: "memory");
}
template<int N>
__device__ __forceinline__ void cp_wait() {
    asm volatile("cp.async.wait_group %0;" :: "n"(N) : "memory");
}
__device__ __forceinline__ void ldsm4(uint32_t (&r)[4], uint32_t addr) {
    asm volatile("ldmatrix.sync.aligned.m8n8.x4.shared.b16 {%0,%1,%2,%3}, [%4];"
                 : "=r"(r[0]), "=r"(r[1]), "=r"(r[2]), "=r"(r[3]) : "r"(addr));
}
__device__ __forceinline__ void mma_f16(float (&d)[4], const uint32_t (&a)[4],
                                        uint32_t b0, uint32_t b1) {
    asm volatile("mma.sync.aligned.m16n8k16.row.col.f32.f16.f16.f32 "
                 "{%0,%1,%2,%3}, {%4,%5,%6,%7}, {%8,%9}, {%0,%1,%2,%3};"
                 : "+f"(d[0]), "+f"(d[1]), "+f"(d[2]), "+f"(d[3])
                 : "r"(a[0]), "r"(a[1]), "r"(a[2]), "r"(a[3]), "r"(b0), "r"(b1));
}
__device__ __forceinline__ uint32_t pack_h2(f16 a, f16 b) {
    __half2 t = __halves2half2(a, b);
    return *reinterpret_cast<uint32_t*>(&t);
}

// ---------------------------------------------------------------------------
// batched weight convert fp32 -> fp16: up to 4 arrays (sizes in float4 units)
// ---------------------------------------------------------------------------
__global__ __launch_bounds__(256) void conv_multi(
    const float* __restrict__ s0, f16* __restrict__ d0, int n0,
    const float* __restrict__ s1, f16* __restrict__ d1, int n1,
    const float* __restrict__ s2, f16* __restrict__ d2, int n2,
    const float* __restrict__ s3, f16* __restrict__ d3, int n3)
{
    int i = blockIdx.x * 256 + threadIdx.x;
    const float* s; f16* d; int j = i;
    if (j < n0) { s = s0; d = d0; }
    else {
        j -= n0;
        if (j < n1) { s = s1; d = d1; }
        else {
            j -= n1;
            if (j < n2) { s = s2; d = d2; }
            else {
                j -= n2;
                if (j >= n3) return;
                s = s3; d = d3;
            }
        }
    }
    float4 v = reinterpret_cast<const float4*>(s)[j];
    reinterpret_cast<uint2*>(d)[j] = make_uint2(
        pack_h2(__float2half(v.x), __float2half(v.y)),
        pack_h2(__float2half(v.z), __float2half(v.w)));
}

// ---------------------------------------------------------------------------
// RMSNorm -> fp16
// ---------------------------------------------------------------------------
__global__ __launch_bounds__(256) void rmsnorm_h16(
    const float* __restrict__ x, const float* __restrict__ w,
    f16* __restrict__ o)
{
    int tkn = blockIdx.x;
    int t = threadIdx.x;
    float4 v = reinterpret_cast<const float4*>(x + (size_t)tkn * HIDDEN)[t];
    float s = v.x * v.x + v.y * v.y + v.z * v.z + v.w * v.w;
    #pragma unroll
    for (int o2 = 16; o2 > 0; o2 >>= 1) s += __shfl_xor_sync(0xFFFFFFFFu, s, o2);
    __shared__ float ws[8];
    __shared__ float tot_sh;
    if ((t & 31) == 0) ws[t >> 5] = s;
    __syncthreads();
    if (t < 32) {
        float z = (t < 8) ? ws[t] : 0.0f;
        #pragma unroll
        for (int o2 = 4; o2 > 0; o2 >>= 1) z += __shfl_xor_sync(0xFFFFFFFFu, z, o2);
        if (t == 0) tot_sh = z;
    }
    __syncthreads();
    float r = rsqrtf(tot_sh * (1.0f / HIDDEN) + 1e-6f);
    float4 wv = reinterpret_cast<const float4*>(w)[t];
    size_t q = (size_t)tkn * (HIDDEN / 4) + t;
    reinterpret_cast<uint2*>(o)[q] = make_uint2(
        pack_h2(__float2half(v.x * r * wv.x), __float2half(v.y * r * wv.y)),
        pack_h2(__float2half(v.z * r * wv.z), __float2half(v.w * r * wv.w)));
}

// ---------------------------------------------------------------------------
// GEMM: C[N=16384, M] = A[N,K] @ W[M,K]^T, fp16 in, fp32 accum.
// CTA tile 128x256, 8 warps (64x64 warp tiles, 2x4 grid), BK=64.
// 4-stage cp.async (48KB/stage: A 16KB + B 32KB), depth-3 prefetch,
// one __syncthreads per chunk.
// ---------------------------------------------------------------------------
#define EPI_NONE          0
#define EPI_SIGMOID       1
#define EPI_BIAS_SIGMOID  2
#define EPI_RESADD        3
#define EPI_SILU_AUX_MUL  4

template<int EPI>
__device__ __forceinline__ float epi_apply(float v, const float* __restrict__ aux,
                                           size_t idx, int col)
{
    if (EPI == EPI_SIGMOID)      return 1.0f / (1.0f + expf(-v));
    if (EPI == EPI_BIAS_SIGMOID) { float z = v + __ldg(&aux[col]);
                                   return 1.0f / (1.0f + expf(-z)); }
    if (EPI == EPI_RESADD)       return v + __ldg(&aux[idx]);
    if (EPI == EPI_SILU_AUX_MUL) { float g = __ldg(&aux[idx]);
                                   return v * (g / (1.0f + expf(-g))); }
    return v;
}

#define STAGE_B   49152u
#define GEMM_SMEM (4 * 49152)

template<int EPI, bool OUT16>
__global__ __launch_bounds__(256, 1) void mma_gemm(
    const f16* __restrict__ A, const f16* __restrict__ B,
    float* __restrict__ Cf, f16* __restrict__ Ch,
    const float* __restrict__ aux, int M, int K)
{
    extern __shared__ char smem[];
    const uint32_t sb = smem_u32(smem);
    const int tid = threadIdx.x;
    const int lane = tid & 31;
    const int wid = tid >> 5;
    const int warp_m = wid >> 2;    // 0..1  (64 rows each)
    const int warp_n = wid & 3;     // 0..3  (64 cols each)
    const int rowBlock = blockIdx.y * 128;
    const int colBlock = blockIdx.x * 256;
    const int nch = K >> 6;

    const f16* gpA = A + (size_t)rowBlock * K;
    const f16* gpB = B + (size_t)colBlock * K;

    auto issue = [&](int buf, int c) {
        const int kb = c * 64;
        uint32_t st = sb + (uint32_t)buf * STAGE_B;
        // A: 128 rows x 64 k fp16 = 1024 x 16B
        #pragma unroll
        for (int i = 0; i < 4; i++) {
            int u = tid + i * 256;
            int r = u >> 3, cc = u & 7;
            cp16(st + r * 128 + ((cc ^ (r & 7)) << 4),
                 gpA + (size_t)r * K + kb + cc * 8);
        }
        // B: 256 rows x 64 k fp16 = 2048 x 16B
        #pragma unroll
        for (int i = 0; i < 8; i++) {
            int u = tid + i * 256;
            int r = u >> 3, cc = u & 7;
            cp16(st + 16384u + r * 128 + ((cc ^ (r & 7)) << 4),
                 gpB + (size_t)r * K + kb + cc * 8);
        }
        cp_commit();
    };

    float acc[4][8][4];
    #pragma unroll
    for (int i = 0; i < 4; i++)
        #pragma unroll
        for (int j = 0; j < 8; j++)
            #pragma unroll
            for (int k = 0; k < 4; k++) acc[i][j][k] = 0.0f;

    issue(0, 0);
    if (nch > 1) issue(1, 1);
    if (nch > 2) issue(2, 2);

    // lane-level ldmatrix addressing (row&7 == lane&7)
    const int aRow0 = warp_m * 64 + (lane & 7) + ((lane >> 3) & 1) * 8;
    const int aKh   = (lane >> 4) & 1;
    const int bRow0 = warp_n * 64 + ((lane >> 4) & 1) * 8 + (lane & 7);
    const int bKh   = (lane >> 3) & 1;
    const int swz   = lane & 7;

    for (int c = 0; c < nch; c++) {
        int buf = c & 3;
        int rem = nch - 1 - c;
        if (rem >= 2) cp_wait<2>();
        else if (rem == 1) cp_wait<1>();
        else cp_wait<0>();
        __syncthreads();
        if (c + 3 < nch) issue((c + 3) & 3, c + 3);

        uint32_t st = sb + (uint32_t)buf * STAGE_B;
        #pragma unroll
        for (int ks = 0; ks < 4; ks++) {
            uint32_t afr[4][4];
            #pragma unroll
            for (int mt = 0; mt < 4; mt++) {
                uint32_t roff = (uint32_t)(aRow0 + mt * 16) * 128
                              + (uint32_t)(((ks * 2 + aKh) ^ swz) << 4);
                ldsm4(afr[mt], st + roff);
            }
            uint32_t bfr[8][2];
            #pragma unroll
            for (int p = 0; p < 4; p++) {
                uint32_t roff = (uint32_t)(bRow0 + p * 16) * 128
                              + (uint32_t)(((ks * 2 + bKh) ^ swz) << 4);
                uint32_t t4[4];
                ldsm4(t4, st + 16384u + roff);
                bfr[2 * p][0] = t4[0]; bfr[2 * p][1] = t4[1];
                bfr[2 * p + 1][0] = t4[2]; bfr[2 * p + 1][1] = t4[3];
            }
            #pragma unroll
            for (int mt = 0; mt < 4; mt++)
                #pragma unroll
                for (int nt = 0; nt < 8; nt++)
                    mma_f16(acc[mt][nt], afr[mt], bfr[nt][0], bfr[nt][1]);
        }
        __syncthreads();
    }

    // epilogue
    #pragma unroll
    for (int mt = 0; mt < 4; mt++) {
        #pragma unroll
        for (int nt = 0; nt < 8; nt++) {
            int col = colBlock + warp_n * 64 + nt * 8 + (lane & 3) * 2;
            #pragma unroll
            for (int half = 0; half < 2; half++) {
                int row = rowBlock + warp_m * 64 + mt * 16 + (lane >> 2) + half * 8;
                size_t idx = (size_t)row * M + col;
                float f0 = epi_apply<EPI>(acc[mt][nt][half * 2 + 0], aux, idx, col);
                float f1 = epi_apply<EPI>(acc[mt][nt][half * 2 + 1], aux, idx + 1, col + 1);
                if (OUT16) {
                    *reinterpret_cast<uint32_t*>(Ch + idx) =
                        pack_h2(__float2half(f0), __float2half(f1));
                } else {
                    *reinterpret_cast<float2*>(Cf + idx) = make_float2(f0, f1);
                }
            }
        }
    }
}

// ---------------------------------------------------------------------------
// Parallel Hawk scan (3 passes)
// ---------------------------------------------------------------------------
__global__ __launch_bounds__(256) void scan_part1(
    const f16* __restrict__ xin, const float* __restrict__ a,
    float* __restrict__ hp, float* __restrict__ P, float* __restrict__ csum)
{
    int id = blockIdx.x * 256 + threadIdx.x;
    int chunk = id >> 13;
    int chp = id & (NCHAN - 1);
    int b = chp >> 11;
    int d = chp & (DREC - 1);
    size_t base = ((size_t)b * TLEN + (size_t)chunk * SCHUNK) * DREC + d;

    float h = 0.0f, Aacc = 1.0f;
    #pragma unroll 4
    for (int t = 0; t < SCHUNK; t++) {
        size_t idx = base + (size_t)t * DREC;
        float at = __ldg(&a[idx]);
        float xt = __half2float(__ldg(&xin[idx]));
        float s = sqrtf(fmaf(-at, at, 1.0f) + 1e-8f);
        h = fmaf(at, h, s * xt);
        Aacc *= at;
        hp[idx] = h;
        P[idx] = Aacc;
    }
    csum[(size_t)chunk * NCHAN + chp] = Aacc;
    csum[(size_t)NCHUNKS * NCHAN + (size_t)chunk * NCHAN + chp] = h;
}

__global__ __launch_bounds__(256) void scan_part2(
    const float* __restrict__ csum, float* __restrict__ carry)
{
    int chp = blockIdx.x * 256 + threadIdx.x;
    float h = 0.0f;
    #pragma unroll 8
    for (int c = 0; c < NCHUNKS; c++) {
        carry[(size_t)c * NCHAN + chp] = h;
        float Ac = csum[(size_t)c * NCHAN + chp];
        float hc = csum[(size_t)NCHUNKS * NCHAN + (size_t)c * NCHAN + chp];
        h = fmaf(Ac, h, hc);
    }
}

__global__ __launch_bounds__(256) void scan_part3(
    const float* __restrict__ hp, const float* __restrict__ P,
    const float* __restrict__ gate, const float* __restrict__ carry,
    f16* __restrict__ y)
{
    size_t q = (size_t)blockIdx.x * 256 + threadIdx.x;  // float4 index
    size_t i = q * 4;
    size_t n = i >> 11;
    int d = (int)(i & (DREC - 1));
    int b = (int)(n >> 12);
    int t = (int)(n & (TLEN - 1));
    int c = t >> 6;

    float4 h4 = reinterpret_cast<const float4*>(hp)[q];
    float4 p4 = reinterpret_cast<const float4*>(P)[q];
    float4 g4 = reinterpret_cast<const float4*>(gate)[q];
    float4 cv = *reinterpret_cast<const float4*>(carry + (size_t)c * NCHAN + b * DREC + d);
    float o0 = g4.x * fmaf(p4.x, cv.x, h4.x);
    float o1 = g4.y * fmaf(p4.y, cv.y, h4.y);
    float o2 = g4.z * fmaf(p4.z, cv.z, h4.z);
    float o3 = g4.w * fmaf(p4.w, cv.w, h4.w);
    reinterpret_cast<uint2*>(y)[q] = make_uint2(
        pack_h2(__float2half(o0), __float2half(o1)),
        pack_h2(__float2half(o2), __float2half(o3)));
}

// ---------------------------------------------------------------------------
// Launch
// ---------------------------------------------------------------------------
#define SYM(p, s) cudaGetSymbolAddress((void**)&p, s)

extern "C" void kernel_launch(void* const* d_in, const int* in_sizes, int n_in,
                              void* d_out, int out_size)
{
    const float* x       = (const float*)d_in[0];
    const float* ln1_w   = (const float*)d_in[1];
    const float* ln2_w   = (const float*)d_in[2];
    const float* w_in    = (const float*)d_in[3];
    const float* w_gate  = (const float*)d_in[4];
    const float* a_param = (const float*)d_in[5];
    const float* w_a     = (const float*)d_in[6];
    const float* w_out   = (const float*)d_in[7];
    const float* w_mg    = (const float*)d_in[8];
    const float* w_mu    = (const float*)d_in[9];
    const float* w_md    = (const float*)d_in[10];
    float* out = (float*)d_out;

    f16 *hh, *h2h, *xinh, *yh, *muh;
    float *xres, *gate, *aa, *hp, *P, *mg, *csum, *carry;
    f16 *wi, *wg, *wa, *wo, *wmgp, *wmup, *wmdp;

    SYM(hh, g_h);   SYM(h2h, g_h2);
    SYM(xinh, g_xin); SYM(yh, g_y); SYM(muh, g_mu);
    SYM(xres, g_xres); SYM(gate, g_gate); SYM(aa, g_a);
    SYM(hp, g_hp);     SYM(P, g_P);       SYM(mg, g_mg);
    SYM(csum, g_csum); SYM(carry, g_carry);
    SYM(wi, g_wi);  SYM(wg, g_wg);  SYM(wa, g_wa);  SYM(wo, g_wo);
    SYM(wmgp, g_wmg); SYM(wmup, g_wmu); SYM(wmdp, g_wmd);

    cudaFuncSetAttribute(mma_gemm<EPI_NONE, true>,          cudaFuncAttributeMaxDynamicSharedMemorySize, GEMM_SMEM);
    cudaFuncSetAttribute(mma_gemm<EPI_NONE, false>,         cudaFuncAttributeMaxDynamicSharedMemorySize, GEMM_SMEM);
    cudaFuncSetAttribute(mma_gemm<EPI_SIGMOID, false>,      cudaFuncAttributeMaxDynamicSharedMemorySize, GEMM_SMEM);
    cudaFuncSetAttribute(mma_gemm<EPI_BIAS_SIGMOID, false>, cudaFuncAttributeMaxDynamicSharedMemorySize, GEMM_SMEM);
    cudaFuncSetAttribute(mma_gemm<EPI_RESADD, false>,       cudaFuncAttributeMaxDynamicSharedMemorySize, GEMM_SMEM);
    cudaFuncSetAttribute(mma_gemm<EPI_SILU_AUX_MUL, true>,  cudaFuncAttributeMaxDynamicSharedMemorySize, GEMM_SMEM);

    dim3 blk(256);
    const int GY = NTOK / 128;   // 128

    const int n_ih = DREC * HIDDEN / 4;   // 524288
    const int n_aa = DREC * DREC / 4;     // 1048576
    const int n_mh = INTER * HIDDEN / 4;  // 1048576

    // launch 0: convert w_in, w_gate, w_a
    conv_multi<<<(n_ih + n_ih + n_aa + 255) / 256, blk>>>(
        w_in, wi, n_ih, w_gate, wg, n_ih, w_a, wa, n_aa, w_a, wa, 0);
    // launch 1: convert w_out, w_mg, w_mu, w_md
    conv_multi<<<(n_ih + 3 * n_mh + 255) / 256, blk>>>(
        w_out, wo, n_ih, w_mg, wmgp, n_mh, w_mu, wmup, n_mh, w_md, wmdp, n_mh);

    // launch 2: h = rmsnorm(x, ln1)
    rmsnorm_h16<<<NTOK, blk>>>(x, ln1_w, hh);

    // launch 3: xin = h @ w_in^T
    mma_gemm<EPI_NONE, true><<<dim3(DREC / 256, GY), blk, GEMM_SMEM>>>(
        hh, wi, nullptr, xinh, nullptr, DREC, HIDDEN);

    // launch 4: gate = sigmoid(h @ w_gate^T)
    mma_gemm<EPI_SIGMOID, false><<<dim3(DREC / 256, GY), blk, GEMM_SMEM>>>(
        hh, wg, gate, nullptr, nullptr, DREC, HIDDEN);

    // launch 5 (ncu profiles this): a = sigmoid(a_param + xin @ w_a^T)
    mma_gemm<EPI_BIAS_SIGMOID, false><<<dim3(DREC / 256, GY), blk, GEMM_SMEM>>>(
        xinh, wa, aa, nullptr, a_param, DREC, DREC);

    // scan
    scan_part1<<<(NCHUNKS * NCHAN) / 256, blk>>>(xinh, aa, hp, P, csum);
    scan_part2<<<NCHAN / 256, blk>>>(csum, carry);
    scan_part3<<<(int)((size_t)NTOK * DREC / 4 / 256), blk>>>(hp, P, gate, carry, yh);

    // xres = x + y @ w_out^T
    mma_gemm<EPI_RESADD, false><<<dim3(HIDDEN / 256, GY), blk, GEMM_SMEM>>>(
        yh, wo, xres, nullptr, x, HIDDEN, DREC);

    // h2 = rmsnorm(xres, ln2)
    rmsnorm_h16<<<NTOK, blk>>>(xres, ln2_w, h2h);

    // mg = h2 @ w_mlp_gate^T
    mma_gemm<EPI_NONE, false><<<dim3(INTER / 256, GY), blk, GEMM_SMEM>>>(
        h2h, wmgp, mg, nullptr, nullptr, INTER, HIDDEN);

    // mu = silu(mg) * (h2 @ w_mlp_up^T)
    mma_gemm<EPI_SILU_AUX_MUL, true><<<dim3(INTER / 256, GY), blk, GEMM_SMEM>>>(
        h2h, wmup, nullptr, muh, mg, INTER, HIDDEN);

    // out = xres + mu @ w_mlp_down^T
    mma_gemm<EPI_RESADD, false><<<dim3(HIDDEN / 256, GY), blk, GEMM_SMEM>>>(
        muh, wmdp, out, nullptr, xres, HIDDEN, INTER);
}

// round 7
// speedup vs baseline: 2.5799x; 1.1990x over previous
#include <cuda_runtime.h>
#include <cuda_fp16.h>
#include <math.h>
#include <stdint.h>

// ---------------------------------------------------------------------------
// HawkBlock: fp16 mma.sync GEMMs (CTA 128x128, 4 warps @ 64x64, 3-stage
// cp.async, 2 CTAs/SM) + recompute-style parallel scan.
// ---------------------------------------------------------------------------

#define NTOK   16384
#define HIDDEN 1024
#define DREC   2048
#define INTER  4096
#define TLEN   4096
#define NB     4

#define SCHUNK   64
#define NCHUNKS  (TLEN / SCHUNK)   // 64
#define NCHAN    (NB * DREC)       // 8192

typedef __half f16;

// ---- static scratch ----
__device__ f16   g_h   [(size_t)NTOK * HIDDEN];
__device__ f16   g_h2  [(size_t)NTOK * HIDDEN];
__device__ float g_xres[(size_t)NTOK * HIDDEN];
__device__ f16   g_xin [(size_t)NTOK * DREC];
__device__ f16   g_gate[(size_t)NTOK * DREC];
__device__ float g_a   [(size_t)NTOK * DREC];
__device__ f16   g_y   [(size_t)NTOK * DREC];
__device__ f16   g_mg  [(size_t)NTOK * INTER];
__device__ f16   g_mu  [(size_t)NTOK * INTER];
__device__ float g_csum [2 * NCHUNKS * NCHAN];
__device__ float g_carry[NCHUNKS * NCHAN];

// ---- fp16 weights ----
__device__ f16 g_wi [(size_t)DREC * HIDDEN];
__device__ f16 g_wg [(size_t)DREC * HIDDEN];
__device__ f16 g_wa [(size_t)DREC * DREC];
__device__ f16 g_wo [(size_t)HIDDEN * DREC];
__device__ f16 g_wmg[(size_t)INTER * HIDDEN];
__device__ f16 g_wmu[(size_t)INTER * HIDDEN];
__device__ f16 g_wmd[(size_t)HIDDEN * INTER];

// ---------------------------------------------------------------------------
// helpers
// ---------------------------------------------------------------------------
__device__ __forceinline__ uint32_t smem_u32(const void* p) {
    uint32_t a;
    asm("{ .reg .u64 t; cvta.to.shared.u64 t, %1; cvt.u32.u64 %0, t; }"
        : "=r"(a) : "l"(p));
    return a;
}
__device__ __forceinline__ void cp16(uint32_t dst, const void* src) {
    asm volatile("cp.async.cg.shared.global [%0], [%1], 16;"
                 :: "r"(dst), "l"(src));
}
__device__ __forceinline__ void cp_commit() {
    asm volatile("cp.async.commit_group;" ::: "memory");
}
template<int N>
__device__ __forceinline__ void cp_wait() {
    asm volatile("cp.async.wait_group %0;" :: "n"(N) : "memory");
}
__device__ __forceinline__ void ldsm4(uint32_t (&r)[4], uint32_t addr) {
    asm volatile("ldmatrix.sync.aligned.m8n8.x4.shared.b16 {%0,%1,%2,%3}, [%4];"
                 : "=r"(r[0]), "=r"(r[1]), "=r"(r[2]), "=r"(r[3]) : "r"(addr));
}
__device__ __forceinline__ void mma_f16(float (&d)[4], const uint32_t (&a)[4],
                                        uint32_t b0, uint32_t b1) {
    asm volatile("mma.sync.aligned.m16n8k16.row.col.f32.f16.f16.f32 "
                 "{%0,%1,%2,%3}, {%4,%5,%6,%7}, {%8,%9}, {%0,%1,%2,%3};"
                 : "+f"(d[0]), "+f"(d[1]), "+f"(d[2]), "+f"(d[3])
                 : "r"(a[0]), "r"(a[1]), "r"(a[2]), "r"(a[3]), "r"(b0), "r"(b1));
}
__device__ __forceinline__ uint32_t pack_h2(f16 a, f16 b) {
    __half2 t = __halves2half2(a, b);
    return *reinterpret_cast<uint32_t*>(&t);
}

// ---------------------------------------------------------------------------
// batched weight convert fp32 -> fp16
// ---------------------------------------------------------------------------
__global__ __launch_bounds__(256) void conv_multi(
    const float* __restrict__ s0, f16* __restrict__ d0, int n0,
    const float* __restrict__ s1, f16* __restrict__ d1, int n1,
    const float* __restrict__ s2, f16* __restrict__ d2, int n2,
    const float* __restrict__ s3, f16* __restrict__ d3, int n3)
{
    int i = blockIdx.x * 256 + threadIdx.x;
    const float* s; f16* d; int j = i;
    if (j < n0) { s = s0; d = d0; }
    else {
        j -= n0;
        if (j < n1) { s = s1; d = d1; }
        else {
            j -= n1;
            if (j < n2) { s = s2; d = d2; }
            else {
                j -= n2;
                if (j >= n3) return;
                s = s3; d = d3;
            }
        }
    }
    float4 v = reinterpret_cast<const float4*>(s)[j];
    reinterpret_cast<uint2*>(d)[j] = make_uint2(
        pack_h2(__float2half(v.x), __float2half(v.y)),
        pack_h2(__float2half(v.z), __float2half(v.w)));
}

// ---------------------------------------------------------------------------
// RMSNorm -> fp16
// ---------------------------------------------------------------------------
__global__ __launch_bounds__(256) void rmsnorm_h16(
    const float* __restrict__ x, const float* __restrict__ w,
    f16* __restrict__ o)
{
    int tkn = blockIdx.x;
    int t = threadIdx.x;
    float4 v = reinterpret_cast<const float4*>(x + (size_t)tkn * HIDDEN)[t];
    float s = v.x * v.x + v.y * v.y + v.z * v.z + v.w * v.w;
    #pragma unroll
    for (int o2 = 16; o2 > 0; o2 >>= 1) s += __shfl_xor_sync(0xFFFFFFFFu, s, o2);
    __shared__ float ws[8];
    __shared__ float tot_sh;
    if ((t & 31) == 0) ws[t >> 5] = s;
    __syncthreads();
    if (t < 32) {
        float z = (t < 8) ? ws[t] : 0.0f;
        #pragma unroll
        for (int o2 = 4; o2 > 0; o2 >>= 1) z += __shfl_xor_sync(0xFFFFFFFFu, z, o2);
        if (t == 0) tot_sh = z;
    }
    __syncthreads();
    float r = rsqrtf(tot_sh * (1.0f / HIDDEN) + 1e-6f);
    float4 wv = reinterpret_cast<const float4*>(w)[t];
    size_t q = (size_t)tkn * (HIDDEN / 4) + t;
    reinterpret_cast<uint2*>(o)[q] = make_uint2(
        pack_h2(__float2half(v.x * r * wv.x), __float2half(v.y * r * wv.y)),
        pack_h2(__float2half(v.z * r * wv.z), __float2half(v.w * r * wv.w)));
}

// ---------------------------------------------------------------------------
// GEMM: C[N=16384, M] = A[N,K] @ W[M,K]^T, fp16 in, fp32 accum.
// CTA 128x128, 4 warps (64x64 warp tiles), BK=64, 3-stage cp.async (32KB
// each, 96KB total -> 2 CTAs/SM), one __syncthreads per chunk.
// ---------------------------------------------------------------------------
#define EPI_NONE          0
#define EPI_SIGMOID       1
#define EPI_BIAS_SIGMOID  2
#define EPI_RESADD        3
#define EPI_SILU_AUX_MUL  4   // auxh = mg (f16)

template<int EPI>
__device__ __forceinline__ float epi_apply(float v,
                                           const float* __restrict__ auxf,
                                           const f16* __restrict__ auxh,
                                           size_t idx, int col)
{
    if (EPI == EPI_SIGMOID)      return 1.0f / (1.0f + expf(-v));
    if (EPI == EPI_BIAS_SIGMOID) { float z = v + __ldg(&auxf[col]);
                                   return 1.0f / (1.0f + expf(-z)); }
    if (EPI == EPI_RESADD)       return v + __ldg(&auxf[idx]);
    if (EPI == EPI_SILU_AUX_MUL) { float g = __half2float(__ldg(&auxh[idx]));
                                   return v * (g / (1.0f + expf(-g))); }
    return v;
}

#define STAGE_B   32768u
#define GEMM_SMEM (3 * 32768)

template<int EPI, bool OUT16>
__global__ __launch_bounds__(128, 2) void mma_gemm(
    const f16* __restrict__ A, const f16* __restrict__ B,
    float* __restrict__ Cf, f16* __restrict__ Ch,
    const float* __restrict__ auxf, const f16* __restrict__ auxh,
    int M, int K)
{
    extern __shared__ char smem[];
    const uint32_t sb = smem_u32(smem);
    const int tid = threadIdx.x;
    const int lane = tid & 31;
    const int wid = tid >> 5;
    const int warp_m = wid >> 1;    // 0..1
    const int warp_n = wid & 1;     // 0..1
    const int rowBlock = blockIdx.y * 128;
    const int colBlock = blockIdx.x * 128;
    const int nch = K >> 6;

    const f16* gpA = A + (size_t)rowBlock * K;
    const f16* gpB = B + (size_t)colBlock * K;

    auto issue = [&](int buf, int c) {
        const int kb = c * 64;
        uint32_t st = sb + (uint32_t)buf * STAGE_B;
        // A: 128 rows x 64 k = 1024 x 16B lines
        #pragma unroll
        for (int i = 0; i < 8; i++) {
            int u = tid + i * 128;
            int r = u >> 3, cc = u & 7;
            cp16(st + r * 128 + ((cc ^ (r & 7)) << 4),
                 gpA + (size_t)r * K + kb + cc * 8);
        }
        // B: 128 rows x 64 k
        #pragma unroll
        for (int i = 0; i < 8; i++) {
            int u = tid + i * 128;
            int r = u >> 3, cc = u & 7;
            cp16(st + 16384u + r * 128 + ((cc ^ (r & 7)) << 4),
                 gpB + (size_t)r * K + kb + cc * 8);
        }
        cp_commit();
    };

    float acc[4][8][4];
    #pragma unroll
    for (int i = 0; i < 4; i++)
        #pragma unroll
        for (int j = 0; j < 8; j++)
            #pragma unroll
            for (int k = 0; k < 4; k++) acc[i][j][k] = 0.0f;

    issue(0, 0);
    if (nch > 1) issue(1, 1);

    // lane-level ldmatrix addressing (row&7 == lane&7)
    const int aRow0 = warp_m * 64 + (lane & 7) + ((lane >> 3) & 1) * 8;
    const int aKh   = (lane >> 4) & 1;
    const int bRow0 = warp_n * 64 + ((lane >> 4) & 1) * 8 + (lane & 7);
    const int bKh   = (lane >> 3) & 1;
    const int swz   = lane & 7;

    for (int c = 0; c < nch; c++) {
        int buf = c % 3;
        if (c + 1 < nch) cp_wait<1>(); else cp_wait<0>();
        __syncthreads();
        if (c + 2 < nch) issue((c + 2) % 3, c + 2);

        uint32_t st = sb + (uint32_t)buf * STAGE_B;
        #pragma unroll
        for (int ks = 0; ks < 4; ks++) {
            uint32_t afr[4][4];
            #pragma unroll
            for (int mt = 0; mt < 4; mt++) {
                uint32_t roff = (uint32_t)(aRow0 + mt * 16) * 128
                              + (uint32_t)(((ks * 2 + aKh) ^ swz) << 4);
                ldsm4(afr[mt], st + roff);
            }
            uint32_t bfr[8][2];
            #pragma unroll
            for (int p = 0; p < 4; p++) {
                uint32_t roff = (uint32_t)(bRow0 + p * 16) * 128
                              + (uint32_t)(((ks * 2 + bKh) ^ swz) << 4);
                uint32_t t4[4];
                ldsm4(t4, st + 16384u + roff);
                bfr[2 * p][0] = t4[0]; bfr[2 * p][1] = t4[1];
                bfr[2 * p + 1][0] = t4[2]; bfr[2 * p + 1][1] = t4[3];
            }
            #pragma unroll
            for (int mt = 0; mt < 4; mt++)
                #pragma unroll
                for (int nt = 0; nt < 8; nt++)
                    mma_f16(acc[mt][nt], afr[mt], bfr[nt][0], bfr[nt][1]);
        }
    }

    // epilogue
    #pragma unroll
    for (int mt = 0; mt < 4; mt++) {
        #pragma unroll
        for (int nt = 0; nt < 8; nt++) {
            int col = colBlock + warp_n * 64 + nt * 8 + (lane & 3) * 2;
            #pragma unroll
            for (int half = 0; half < 2; half++) {
                int row = rowBlock + warp_m * 64 + mt * 16 + (lane >> 2) + half * 8;
                size_t idx = (size_t)row * M + col;
                float f0 = epi_apply<EPI>(acc[mt][nt][half * 2 + 0], auxf, auxh, idx, col);
                float f1 = epi_apply<EPI>(acc[mt][nt][half * 2 + 1], auxf, auxh, idx + 1, col + 1);
                if (OUT16) {
                    *reinterpret_cast<uint32_t*>(Ch + idx) =
                        pack_h2(__float2half(f0), __float2half(f1));
                } else {
                    *reinterpret_cast<float2*>(Cf + idx) = make_float2(f0, f1);
                }
            }
        }
    }
}

// ---------------------------------------------------------------------------
// Parallel Hawk scan, recompute style (no hp/P intermediates):
// part1: chunk summaries (A_chunk, h_chunk). part2: carries.
// part3: redo local scan seeded with carry, write y = gate*h (f16).
// ---------------------------------------------------------------------------
__global__ __launch_bounds__(256) void scan_part1(
    const f16* __restrict__ xin, const float* __restrict__ a,
    float* __restrict__ csum)
{
    int id = blockIdx.x * 256 + threadIdx.x;
    int chunk = id >> 13;
    int chp = id & (NCHAN - 1);
    int b = chp >> 11;
    int d = chp & (DREC - 1);
    size_t base = ((size_t)b * TLEN + (size_t)chunk * SCHUNK) * DREC + d;

    float h = 0.0f, Aacc = 1.0f;
    #pragma unroll 4
    for (int t = 0; t < SCHUNK; t++) {
        size_t idx = base + (size_t)t * DREC;
        float at = __ldg(&a[idx]);
        float xt = __half2float(__ldg(&xin[idx]));
        float s = sqrtf(fmaf(-at, at, 1.0f) + 1e-8f);
        h = fmaf(at, h, s * xt);
        Aacc *= at;
    }
    csum[(size_t)chunk * NCHAN + chp] = Aacc;
    csum[(size_t)NCHUNKS * NCHAN + (size_t)chunk * NCHAN + chp] = h;
}

__global__ __launch_bounds__(256) void scan_part2(
    const float* __restrict__ csum, float* __restrict__ carry)
{
    int chp = blockIdx.x * 256 + threadIdx.x;
    float h = 0.0f;
    #pragma unroll 8
    for (int c = 0; c < NCHUNKS; c++) {
        carry[(size_t)c * NCHAN + chp] = h;
        float Ac = csum[(size_t)c * NCHAN + chp];
        float hc = csum[(size_t)NCHUNKS * NCHAN + (size_t)c * NCHAN + chp];
        h = fmaf(Ac, h, hc);
    }
}

__global__ __launch_bounds__(256) void scan_part3(
    const f16* __restrict__ xin, const float* __restrict__ a,
    const f16* __restrict__ gate, const float* __restrict__ carry,
    f16* __restrict__ y)
{
    int id = blockIdx.x * 256 + threadIdx.x;
    int chunk = id >> 13;
    int chp = id & (NCHAN - 1);
    int b = chp >> 11;
    int d = chp & (DREC - 1);
    size_t base = ((size_t)b * TLEN + (size_t)chunk * SCHUNK) * DREC + d;

    float h = __ldg(&carry[(size_t)chunk * NCHAN + chp]);
    #pragma unroll 4
    for (int t = 0; t < SCHUNK; t++) {
        size_t idx = base + (size_t)t * DREC;
        float at = __ldg(&a[idx]);
        float xt = __half2float(__ldg(&xin[idx]));
        float gt = __half2float(__ldg(&gate[idx]));
        float s = sqrtf(fmaf(-at, at, 1.0f) + 1e-8f);
        h = fmaf(at, h, s * xt);
        y[idx] = __float2half(gt * h);
    }
}

// ---------------------------------------------------------------------------
// Launch
// ---------------------------------------------------------------------------
#define SYM(p, s) cudaGetSymbolAddress((void**)&p, s)

extern "C" void kernel_launch(void* const* d_in, const int* in_sizes, int n_in,
                              void* d_out, int out_size)
{
    const float* x       = (const float*)d_in[0];
    const float* ln1_w   = (const float*)d_in[1];
    const float* ln2_w   = (const float*)d_in[2];
    const float* w_in    = (const float*)d_in[3];
    const float* w_gate  = (const float*)d_in[4];
    const float* a_param = (const float*)d_in[5];
    const float* w_a     = (const float*)d_in[6];
    const float* w_out   = (const float*)d_in[7];
    const float* w_mg    = (const float*)d_in[8];
    const float* w_mu    = (const float*)d_in[9];
    const float* w_md    = (const float*)d_in[10];
    float* out = (float*)d_out;

    f16 *hh, *h2h, *xinh, *gateh, *yh, *mgh, *muh;
    float *xres, *aa, *csum, *carry;
    f16 *wi, *wg, *wa, *wo, *wmgp, *wmup, *wmdp;

    SYM(hh, g_h);     SYM(h2h, g_h2);
    SYM(xinh, g_xin); SYM(gateh, g_gate);
    SYM(yh, g_y);     SYM(mgh, g_mg);    SYM(muh, g_mu);
    SYM(xres, g_xres); SYM(aa, g_a);
    SYM(csum, g_csum); SYM(carry, g_carry);
    SYM(wi, g_wi);  SYM(wg, g_wg);  SYM(wa, g_wa);  SYM(wo, g_wo);
    SYM(wmgp, g_wmg); SYM(wmup, g_wmu); SYM(wmdp, g_wmd);

    cudaFuncSetAttribute(mma_gemm<EPI_NONE, true>,          cudaFuncAttributeMaxDynamicSharedMemorySize, GEMM_SMEM);
    cudaFuncSetAttribute(mma_gemm<EPI_SIGMOID, true>,       cudaFuncAttributeMaxDynamicSharedMemorySize, GEMM_SMEM);
    cudaFuncSetAttribute(mma_gemm<EPI_BIAS_SIGMOID, false>, cudaFuncAttributeMaxDynamicSharedMemorySize, GEMM_SMEM);
    cudaFuncSetAttribute(mma_gemm<EPI_RESADD, false>,       cudaFuncAttributeMaxDynamicSharedMemorySize, GEMM_SMEM);
    cudaFuncSetAttribute(mma_gemm<EPI_SILU_AUX_MUL, true>,  cudaFuncAttributeMaxDynamicSharedMemorySize, GEMM_SMEM);

    dim3 blk(256);
    dim3 gblk(128);
    const int GY = NTOK / 128;   // 128

    const int n_ih = DREC * HIDDEN / 4;   // 524288
    const int n_aa = DREC * DREC / 4;     // 1048576
    const int n_mh = INTER * HIDDEN / 4;  // 1048576

    // launch 0-1: weight conversion
    conv_multi<<<(n_ih + n_ih + n_aa + 255) / 256, blk>>>(
        w_in, wi, n_ih, w_gate, wg, n_ih, w_a, wa, n_aa, w_a, wa, 0);
    conv_multi<<<(n_ih + 3 * n_mh + 255) / 256, blk>>>(
        w_out, wo, n_ih, w_mg, wmgp, n_mh, w_mu, wmup, n_mh, w_md, wmdp, n_mh);

    // launch 2: h = rmsnorm(x, ln1)
    rmsnorm_h16<<<NTOK, blk>>>(x, ln1_w, hh);

    // launch 3: xin = h @ w_in^T
    mma_gemm<EPI_NONE, true><<<dim3(DREC / 128, GY), gblk, GEMM_SMEM>>>(
        hh, wi, nullptr, xinh, nullptr, nullptr, DREC, HIDDEN);

    // launch 4: gate = sigmoid(h @ w_gate^T)  (f16)
    mma_gemm<EPI_SIGMOID, true><<<dim3(DREC / 128, GY), gblk, GEMM_SMEM>>>(
        hh, wg, nullptr, gateh, nullptr, nullptr, DREC, HIDDEN);

    // launch 5 (ncu profiles this): a = sigmoid(a_param + xin @ w_a^T)  (f32)
    mma_gemm<EPI_BIAS_SIGMOID, false><<<dim3(DREC / 128, GY), gblk, GEMM_SMEM>>>(
        xinh, wa, aa, nullptr, a_param, nullptr, DREC, DREC);

    // scan
    scan_part1<<<(NCHUNKS * NCHAN) / 256, blk>>>(xinh, aa, csum);
    scan_part2<<<NCHAN / 256, blk>>>(csum, carry);
    scan_part3<<<(NCHUNKS * NCHAN) / 256, blk>>>(xinh, aa, gateh, carry, yh);

    // xres = x + y @ w_out^T
    mma_gemm<EPI_RESADD, false><<<dim3(HIDDEN / 128, GY), gblk, GEMM_SMEM>>>(
        yh, wo, xres, nullptr, x, nullptr, HIDDEN, DREC);

    // h2 = rmsnorm(xres, ln2)
    rmsnorm_h16<<<NTOK, blk>>>(xres, ln2_w, h2h);

    // mg = h2 @ w_mlp_gate^T  (f16)
    mma_gemm<EPI_NONE, true><<<dim3(INTER / 128, GY), gblk, GEMM_SMEM>>>(
        h2h, wmgp, nullptr, mgh, nullptr, nullptr, INTER, HIDDEN);

    // mu = silu(mg) * (h2 @ w_mlp_up^T)  (f16)
    mma_gemm<EPI_SILU_AUX_MUL, true><<<dim3(INTER / 128, GY), gblk, GEMM_SMEM>>>(
        h2h, wmup, nullptr, muh, nullptr, mgh, INTER, HIDDEN);

    // out = xres + mu @ w_mlp_down^T
    mma_gemm<EPI_RESADD, false><<<dim3(HIDDEN / 128, GY), gblk, GEMM_SMEM>>>(
        muh, wmdp, out, nullptr, xres, nullptr, HIDDEN, INTER);
}

// round 9
// speedup vs baseline: 2.6906x; 1.0429x over previous
#include <cuda_runtime.h>
#include <cuda_fp16.h>
#include <math.h>
#include <stdint.h>

// ---------------------------------------------------------------------------
// HawkBlock: fp16 mma.sync GEMMs, f32 accum (CTA 128x128, 4 warps @ 64x64,
// 3-stage mbarrier producer/consumer ring, 2 CTAs/SM) + parallel scan.
// ---------------------------------------------------------------------------

#define NTOK   16384
#define HIDDEN 1024
#define DREC   2048
#define INTER  4096
#define TLEN   4096
#define NB     4

#define SCHUNK   64
#define NCHUNKS  (TLEN / SCHUNK)   // 64
#define NCHAN    (NB * DREC)       // 8192

typedef __half f16;

// ---- static scratch ----
__device__ f16   g_h   [(size_t)NTOK * HIDDEN];
__device__ f16   g_h2  [(size_t)NTOK * HIDDEN];
__device__ float g_xres[(size_t)NTOK * HIDDEN];
__device__ f16   g_xin [(size_t)NTOK * DREC];
__device__ f16   g_gate[(size_t)NTOK * DREC];
__device__ float g_a   [(size_t)NTOK * DREC];
__device__ f16   g_y   [(size_t)NTOK * DREC];
__device__ f16   g_mg  [(size_t)NTOK * INTER];
__device__ f16   g_mu  [(size_t)NTOK * INTER];
__device__ float g_csum [2 * NCHUNKS * NCHAN];
__device__ float g_carry[NCHUNKS * NCHAN];

// ---- fp16 weights ----
__device__ f16 g_wi [(size_t)DREC * HIDDEN];
__device__ f16 g_wg [(size_t)DREC * HIDDEN];
__device__ f16 g_wa [(size_t)DREC * DREC];
__device__ f16 g_wo [(size_t)HIDDEN * DREC];
__device__ f16 g_wmg[(size_t)INTER * HIDDEN];
__device__ f16 g_wmu[(size_t)INTER * HIDDEN];
__device__ f16 g_wmd[(size_t)HIDDEN * INTER];

// ---------------------------------------------------------------------------
// helpers
// ---------------------------------------------------------------------------
__device__ __forceinline__ uint32_t smem_u32(const void* p) {
    uint32_t a;
    asm("{ .reg .u64 t; cvta.to.shared.u64 t, %1; cvt.u32.u64 %0, t; }"
        : "=r"(a) : "l"(p));
    return a;
}
__device__ __forceinline__ void cp16(uint32_t dst, const void* src) {
    asm volatile("cp.async.cg.shared.global [%0], [%1], 16;"
                 :: "r"(dst), "l"(src));
}
__device__ __forceinline__ void ldsm4(uint32_t (&r)[4], uint32_t addr) {
    asm volatile("ldmatrix.sync.aligned.m8n8.x4.shared.b16 {%0,%1,%2,%3}, [%4];"
                 : "=r"(r[0]), "=r"(r[1]), "=r"(r[2]), "=r"(r[3]) : "r"(addr));
}
__device__ __forceinline__ void mma_f16(float (&d)[4], const uint32_t (&a)[4],
                                        uint32_t b0, uint32_t b1) {
    asm volatile("mma.sync.aligned.m16n8k16.row.col.f32.f16.f16.f32 "
                 "{%0,%1,%2,%3}, {%4,%5,%6,%7}, {%8,%9}, {%0,%1,%2,%3};"
                 : "+f"(d[0]), "+f"(d[1]), "+f"(d[2]), "+f"(d[3])
                 : "r"(a[0]), "r"(a[1]), "r"(a[2]), "r"(a[3]), "r"(b0), "r"(b1));
}
__device__ __forceinline__ uint32_t pack_h2(f16 a, f16 b) {
    __half2 t = __halves2half2(a, b);
    return *reinterpret_cast<uint32_t*>(&t);
}

// ---- mbarrier primitives ----
#define MBAR_INIT(addr, cnt) \
    asm volatile("mbarrier.init.shared.b64 [%0], %1;" \
                 :: "r"((uint32_t)(addr)), "r"((uint32_t)(cnt)) : "memory")
#define MBAR_ARRIVE(addr) \
    asm volatile("mbarrier.arrive.shared.b64 _, [%0];" \
                 :: "r"((uint32_t)(addr)) : "memory")
#define CP_MBAR_ARRIVE(addr) \
    asm volatile("cp.async.mbarrier.arrive.noinc.shared.b64 [%0];" \
                 :: "r"((uint32_t)(addr)) : "memory")
#define MBAR_WAIT(addr, parity) do {                                            \
    uint32_t _m = (uint32_t)(addr); uint32_t _p = (uint32_t)(parity);           \
    uint32_t _d;                                                                \
    asm volatile("{\n\t.reg .pred p;\n\t"                                       \
        "mbarrier.try_wait.parity.acquire.cta.shared::cta.b64 p, [%1], %2;\n\t" \
        "selp.b32 %0, 1, 0, p;\n\t}" : "=r"(_d) : "r"(_m), "r"(_p) : "memory"); \
    if (!_d) {                                                                  \
        asm volatile("{\n\t.reg .pred P1;\n\t"                                  \
            "W_%=:\n\t"                                                         \
            "mbarrier.try_wait.parity.acquire.cta.shared::cta.b64 P1, [%0], %1, 0x989680;\n\t" \
            "@P1 bra.uni D_%=;\n\t"                                             \
            "bra.uni W_%=;\n\t"                                                 \
            "D_%=:\n\t}" :: "r"(_m), "r"(_p) : "memory");                       \
    }                                                                           \
} while (0)

// ---------------------------------------------------------------------------
// batched weight convert fp32 -> fp16
// ---------------------------------------------------------------------------
__global__ __launch_bounds__(256) void conv_multi(
    const float* __restrict__ s0, f16* __restrict__ d0, int n0,
    const float* __restrict__ s1, f16* __restrict__ d1, int n1,
    const float* __restrict__ s2, f16* __restrict__ d2, int n2,
    const float* __restrict__ s3, f16* __restrict__ d3, int n3)
{
    int i = blockIdx.x * 256 + threadIdx.x;
    const float* s; f16* d; int j = i;
    if (j < n0) { s = s0; d = d0; }
    else {
        j -= n0;
        if (j < n1) { s = s1; d = d1; }
        else {
            j -= n1;
            if (j < n2) { s = s2; d = d2; }
            else {
                j -= n2;
                if (j >= n3) return;
                s = s3; d = d3;
            }
        }
    }
    float4 v = reinterpret_cast<const float4*>(s)[j];
    reinterpret_cast<uint2*>(d)[j] = make_uint2(
        pack_h2(__float2half(v.x), __float2half(v.y)),
        pack_h2(__float2half(v.z), __float2half(v.w)));
}

// ---------------------------------------------------------------------------
// RMSNorm -> fp16
// ---------------------------------------------------------------------------
__global__ __launch_bounds__(256) void rmsnorm_h16(
    const float* __restrict__ x, const float* __restrict__ w,
    f16* __restrict__ o)
{
    int tkn = blockIdx.x;
    int t = threadIdx.x;
    float4 v = reinterpret_cast<const float4*>(x + (size_t)tkn * HIDDEN)[t];
    float s = v.x * v.x + v.y * v.y + v.z * v.z + v.w * v.w;
    #pragma unroll
    for (int o2 = 16; o2 > 0; o2 >>= 1) s += __shfl_xor_sync(0xFFFFFFFFu, s, o2);
    __shared__ float ws[8];
    __shared__ float tot_sh;
    if ((t & 31) == 0) ws[t >> 5] = s;
    __syncthreads();
    if (t < 32) {
        float z = (t < 8) ? ws[t] : 0.0f;
        #pragma unroll
        for (int o2 = 4; o2 > 0; o2 >>= 1) z += __shfl_xor_sync(0xFFFFFFFFu, z, o2);
        if (t == 0) tot_sh = z;
    }
    __syncthreads();
    float r = rsqrtf(tot_sh * (1.0f / HIDDEN) + 1e-6f);
    float4 wv = reinterpret_cast<const float4*>(w)[t];
    size_t q = (size_t)tkn * (HIDDEN / 4) + t;
    reinterpret_cast<uint2*>(o)[q] = make_uint2(
        pack_h2(__float2half(v.x * r * wv.x), __float2half(v.y * r * wv.y)),
        pack_h2(__float2half(v.z * r * wv.z), __float2half(v.w * r * wv.w)));
}

// ---------------------------------------------------------------------------
// GEMM: C[N=16384, M] = A[N,K] @ W[M,K]^T, fp16 in, fp32 accum.
// CTA 128x128, 4 warps (64x64 warp tiles), BK=64.
// 3-stage ring with mbarrier full/empty pairs — NO per-chunk __syncthreads;
// warps free-run with up to 3 chunks of slack.
// ---------------------------------------------------------------------------
#define EPI_NONE          0
#define EPI_SIGMOID       1
#define EPI_BIAS_SIGMOID  2
#define EPI_RESADD        3
#define EPI_SILU_AUX_MUL  4   // auxh = mg (f16)

template<int EPI>
__device__ __forceinline__ float epi_apply(float v,
                                           const float* __restrict__ auxf,
                                           const f16* __restrict__ auxh,
                                           size_t idx, int col)
{
    if (EPI == EPI_SIGMOID)      return 1.0f / (1.0f + expf(-v));
    if (EPI == EPI_BIAS_SIGMOID) { float z = v + __ldg(&auxf[col]);
                                   return 1.0f / (1.0f + expf(-z)); }
    if (EPI == EPI_RESADD)       return v + __ldg(&auxf[idx]);
    if (EPI == EPI_SILU_AUX_MUL) { float g = __half2float(__ldg(&auxh[idx]));
                                   return v * (g / (1.0f + expf(-g))); }
    return v;
}

#define STAGE_B   32768u
#define GEMM_SMEM (3 * 32768 + 64)

template<int EPI, bool OUT16>
__global__ __launch_bounds__(128, 2) void mma_gemm(
    const f16* __restrict__ A, const f16* __restrict__ B,
    float* __restrict__ Cf, f16* __restrict__ Ch,
    const float* __restrict__ auxf, const f16* __restrict__ auxh,
    int M, int K)
{
    extern __shared__ char smem[];
    const uint32_t sb = smem_u32(smem);
    const uint32_t mb = sb + 3u * STAGE_B;       // full[s]=mb+8s, empty[s]=mb+24+8s
    const int tid = threadIdx.x;
    const int lane = tid & 31;
    const int wid = tid >> 5;
    const int warp_m = wid >> 1;    // 0..1
    const int warp_n = wid & 1;     // 0..1
    const int rowBlock = blockIdx.y * 128;
    const int colBlock = blockIdx.x * 128;
    const int nch = K >> 6;

    const f16* gpA = A + (size_t)rowBlock * K;
    const f16* gpB = B + (size_t)colBlock * K;

    if (tid == 0) {
        #pragma unroll
        for (int s = 0; s < 3; s++) {
            MBAR_INIT(mb + s * 8, 128);        // full: 128 cp.async arrivals
            MBAR_INIT(mb + 24 + s * 8, 128);   // empty: 128 thread arrivals
        }
    }
    __syncthreads();

    auto issue = [&](int c, int buf) {
        const int kb = c * 64;
        uint32_t st = sb + (uint32_t)buf * STAGE_B;
        #pragma unroll
        for (int i = 0; i < 8; i++) {
            int u = tid + i * 128;
            int r = u >> 3, cc = u & 7;
            cp16(st + r * 128 + ((cc ^ (r & 7)) << 4),
                 gpA + (size_t)r * K + kb + cc * 8);
        }
        #pragma unroll
        for (int i = 0; i < 8; i++) {
            int u = tid + i * 128;
            int r = u >> 3, cc = u & 7;
            cp16(st + 16384u + r * 128 + ((cc ^ (r & 7)) << 4),
                 gpB + (size_t)r * K + kb + cc * 8);
        }
    };

    float acc[4][8][4];
    #pragma unroll
    for (int i = 0; i < 4; i++)
        #pragma unroll
        for (int j = 0; j < 8; j++)
            #pragma unroll
            for (int k = 0; k < 4; k++) acc[i][j][k] = 0.0f;

    // producer cursor (phase starts 1: first empty-wait passes on fresh barrier)
    int pstage = 0, pphase = 1;
    // consumer cursor
    int cstage = 0, cphase = 0;

    // prologue: fill all 3 stages
    #pragma unroll
    for (int s = 0; s < 3; s++) {
        if (s < nch) {
            MBAR_WAIT(mb + 24 + pstage * 8, pphase);
            issue(s, pstage);
            CP_MBAR_ARRIVE(mb + pstage * 8);
            pstage++; if (pstage == 3) { pstage = 0; pphase ^= 1; }
        }
    }

    // lane-level ldmatrix addressing (row&7 == lane&7)
    const int aRow0 = warp_m * 64 + (lane & 7) + ((lane >> 3) & 1) * 8;
    const int aKh   = (lane >> 4) & 1;
    const int bRow0 = warp_n * 64 + ((lane >> 4) & 1) * 8 + (lane & 7);
    const int bKh   = (lane >> 3) & 1;
    const int swz   = lane & 7;

    for (int c = 0; c < nch; c++) {
        int s = cstage;
        MBAR_WAIT(mb + s * 8, cphase);
        cstage++; if (cstage == 3) { cstage = 0; cphase ^= 1; }

        uint32_t st = sb + (uint32_t)s * STAGE_B;
        #pragma unroll
        for (int ks = 0; ks < 4; ks++) {
            uint32_t afr[4][4];
            #pragma unroll
            for (int mt = 0; mt < 4; mt++) {
                uint32_t roff = (uint32_t)(aRow0 + mt * 16) * 128
                              + (uint32_t)(((ks * 2 + aKh) ^ swz) << 4);
                ldsm4(afr[mt], st + roff);
            }
            uint32_t bfr[8][2];
            #pragma unroll
            for (int p = 0; p < 4; p++) {
                uint32_t roff = (uint32_t)(bRow0 + p * 16) * 128
                              + (uint32_t)(((ks * 2 + bKh) ^ swz) << 4);
                uint32_t t4[4];
                ldsm4(t4, st + 16384u + roff);
                bfr[2 * p][0] = t4[0]; bfr[2 * p][1] = t4[1];
                bfr[2 * p + 1][0] = t4[2]; bfr[2 * p + 1][1] = t4[3];
            }
            #pragma unroll
            for (int mt = 0; mt < 4; mt++)
                #pragma unroll
                for (int nt = 0; nt < 8; nt++)
                    mma_f16(acc[mt][nt], afr[mt], bfr[nt][0], bfr[nt][1]);
        }

        MBAR_ARRIVE(mb + 24 + s * 8);    // this thread is done reading stage s

        if (c + 3 < nch) {
            MBAR_WAIT(mb + 24 + pstage * 8, pphase);   // all threads done with it
            issue(c + 3, pstage);
            CP_MBAR_ARRIVE(mb + pstage * 8);
            pstage++; if (pstage == 3) { pstage = 0; pphase ^= 1; }
        }
    }

    // epilogue (no CTA sync needed; per-warp independent)
    #pragma unroll
    for (int mt = 0; mt < 4; mt++) {
        #pragma unroll
        for (int nt = 0; nt < 8; nt++) {
            int col = colBlock + warp_n * 64 + nt * 8 + (lane & 3) * 2;
            #pragma unroll
            for (int half = 0; half < 2; half++) {
                int row = rowBlock + warp_m * 64 + mt * 16 + (lane >> 2) + half * 8;
                size_t idx = (size_t)row * M + col;
                float f0 = epi_apply<EPI>(acc[mt][nt][half * 2 + 0], auxf, auxh, idx, col);
                float f1 = epi_apply<EPI>(acc[mt][nt][half * 2 + 1], auxf, auxh, idx + 1, col + 1);
                if (OUT16) {
                    *reinterpret_cast<uint32_t*>(Ch + idx) =
                        pack_h2(__float2half(f0), __float2half(f1));
                } else {
                    *reinterpret_cast<float2*>(Cf + idx) = make_float2(f0, f1);
                }
            }
        }
    }
}

// ---------------------------------------------------------------------------
// Parallel Hawk scan, recompute style
// ---------------------------------------------------------------------------
__global__ __launch_bounds__(256) void scan_part1(
    const f16* __restrict__ xin, const float* __restrict__ a,
    float* __restrict__ csum)
{
    int id = blockIdx.x * 256 + threadIdx.x;
    int chunk = id >> 13;
    int chp = id & (NCHAN - 1);
    int b = chp >> 11;
    int d = chp & (DREC - 1);
    size_t base = ((size_t)b * TLEN + (size_t)chunk * SCHUNK) * DREC + d;

    float h = 0.0f, Aacc = 1.0f;
    #pragma unroll 4
    for (int t = 0; t < SCHUNK; t++) {
        size_t idx = base + (size_t)t * DREC;
        float at = __ldg(&a[idx]);
        float xt = __half2float(__ldg(&xin[idx]));
        float s = sqrtf(fmaf(-at, at, 1.0f) + 1e-8f);
        h = fmaf(at, h, s * xt);
        Aacc *= at;
    }
    csum[(size_t)chunk * NCHAN + chp] = Aacc;
    csum[(size_t)NCHUNKS * NCHAN + (size_t)chunk * NCHAN + chp] = h;
}

__global__ __launch_bounds__(256) void scan_part2(
    const float* __restrict__ csum, float* __restrict__ carry)
{
    int chp = blockIdx.x * 256 + threadIdx.x;
    float h = 0.0f;
    #pragma unroll 8
    for (int c = 0; c < NCHUNKS; c++) {
        carry[(size_t)c * NCHAN + chp] = h;
        float Ac = csum[(size_t)c * NCHAN + chp];
        float hc = csum[(size_t)NCHUNKS * NCHAN + (size_t)c * NCHAN + chp];
        h = fmaf(Ac, h, hc);
    }
}

__global__ __launch_bounds__(256) void scan_part3(
    const f16* __restrict__ xin, const float* __restrict__ a,
    const f16* __restrict__ gate, const float* __restrict__ carry,
    f16* __restrict__ y)
{
    int id = blockIdx.x * 256 + threadIdx.x;
    int chunk = id >> 13;
    int chp = id & (NCHAN - 1);
    int b = chp >> 11;
    int d = chp & (DREC - 1);
    size_t base = ((size_t)b * TLEN + (size_t)chunk * SCHUNK) * DREC + d;

    float h = __ldg(&carry[(size_t)chunk * NCHAN + chp]);
    #pragma unroll 4
    for (int t = 0; t < SCHUNK; t++) {
        size_t idx = base + (size_t)t * DREC;
        float at = __ldg(&a[idx]);
        float xt = __half2float(__ldg(&xin[idx]));
        float gt = __half2float(__ldg(&gate[idx]));
        float s = sqrtf(fmaf(-at, at, 1.0f) + 1e-8f);
        h = fmaf(at, h, s * xt);
        y[idx] = __float2half(gt * h);
    }
}

// ---------------------------------------------------------------------------
// Launch
// ---------------------------------------------------------------------------
#define SYM(p, s) cudaGetSymbolAddress((void**)&p, s)

extern "C" void kernel_launch(void* const* d_in, const int* in_sizes, int n_in,
                              void* d_out, int out_size)
{
    const float* x       = (const float*)d_in[0];
    const float* ln1_w   = (const float*)d_in[1];
    const float* ln2_w   = (const float*)d_in[2];
    const float* w_in    = (const float*)d_in[3];
    const float* w_gate  = (const float*)d_in[4];
    const float* a_param = (const float*)d_in[5];
    const float* w_a     = (const float*)d_in[6];
    const float* w_out   = (const float*)d_in[7];
    const float* w_mg    = (const float*)d_in[8];
    const float* w_mu    = (const float*)d_in[9];
    const float* w_md    = (const float*)d_in[10];
    float* out = (float*)d_out;

    f16 *hh, *h2h, *xinh, *gateh, *yh, *mgh, *muh;
    float *xres, *aa, *csum, *carry;
    f16 *wi, *wg, *wa, *wo, *wmgp, *wmup, *wmdp;

    SYM(hh, g_h);     SYM(h2h, g_h2);
    SYM(xinh, g_xin); SYM(gateh, g_gate);
    SYM(yh, g_y);     SYM(mgh, g_mg);    SYM(muh, g_mu);
    SYM(xres, g_xres); SYM(aa, g_a);
    SYM(csum, g_csum); SYM(carry, g_carry);
    SYM(wi, g_wi);  SYM(wg, g_wg);  SYM(wa, g_wa);  SYM(wo, g_wo);
    SYM(wmgp, g_wmg); SYM(wmup, g_wmu); SYM(wmdp, g_wmd);

    cudaFuncSetAttribute(mma_gemm<EPI_NONE, true>,          cudaFuncAttributeMaxDynamicSharedMemorySize, GEMM_SMEM);
    cudaFuncSetAttribute(mma_gemm<EPI_SIGMOID, true>,       cudaFuncAttributeMaxDynamicSharedMemorySize, GEMM_SMEM);
    cudaFuncSetAttribute(mma_gemm<EPI_BIAS_SIGMOID, false>, cudaFuncAttributeMaxDynamicSharedMemorySize, GEMM_SMEM);
    cudaFuncSetAttribute(mma_gemm<EPI_RESADD, false>,       cudaFuncAttributeMaxDynamicSharedMemorySize, GEMM_SMEM);
    cudaFuncSetAttribute(mma_gemm<EPI_SILU_AUX_MUL, true>,  cudaFuncAttributeMaxDynamicSharedMemorySize, GEMM_SMEM);

    dim3 blk(256);
    dim3 gblk(128);
    const int GY = NTOK / 128;   // 128

    const int n_ih = DREC * HIDDEN / 4;   // 524288
    const int n_aa = DREC * DREC / 4;     // 1048576
    const int n_mh = INTER * HIDDEN / 4;  // 1048576

    // launch 0-1: weight conversion
    conv_multi<<<(n_ih + n_ih + n_aa + 255) / 256, blk>>>(
        w_in, wi, n_ih, w_gate, wg, n_ih, w_a, wa, n_aa, w_a, wa, 0);
    conv_multi<<<(n_ih + 3 * n_mh + 255) / 256, blk>>>(
        w_out, wo, n_ih, w_mg, wmgp, n_mh, w_mu, wmup, n_mh, w_md, wmdp, n_mh);

    // launch 2: h = rmsnorm(x, ln1)
    rmsnorm_h16<<<NTOK, blk>>>(x, ln1_w, hh);

    // launch 3: xin = h @ w_in^T
    mma_gemm<EPI_NONE, true><<<dim3(DREC / 128, GY), gblk, GEMM_SMEM>>>(
        hh, wi, nullptr, xinh, nullptr, nullptr, DREC, HIDDEN);

    // launch 4: gate = sigmoid(h @ w_gate^T)  (f16)
    mma_gemm<EPI_SIGMOID, true><<<dim3(DREC / 128, GY), gblk, GEMM_SMEM>>>(
        hh, wg, nullptr, gateh, nullptr, nullptr, DREC, HIDDEN);

    // launch 5 (ncu profiles this): a = sigmoid(a_param + xin @ w_a^T)  (f32)
    mma_gemm<EPI_BIAS_SIGMOID, false><<<dim3(DREC / 128, GY), gblk, GEMM_SMEM>>>(
        xinh, wa, aa, nullptr, a_param, nullptr, DREC, DREC);

    // scan
    scan_part1<<<(NCHUNKS * NCHAN) / 256, blk>>>(xinh, aa, csum);
    scan_part2<<<NCHAN / 256, blk>>>(csum, carry);
    scan_part3<<<(NCHUNKS * NCHAN) / 256, blk>>>(xinh, aa, gateh, carry, yh);

    // xres = x + y @ w_out^T
    mma_gemm<EPI_RESADD, false><<<dim3(HIDDEN / 128, GY), gblk, GEMM_SMEM>>>(
        yh, wo, xres, nullptr, x, nullptr, HIDDEN, DREC);

    // h2 = rmsnorm(xres, ln2)
    rmsnorm_h16<<<NTOK, blk>>>(xres, ln2_w, h2h);

    // mg = h2 @ w_mlp_gate^T  (f16)
    mma_gemm<EPI_NONE, true><<<dim3(INTER / 128, GY), gblk, GEMM_SMEM>>>(
        h2h, wmgp, nullptr, mgh, nullptr, nullptr, INTER, HIDDEN);

    // mu = silu(mg) * (h2 @ w_mlp_up^T)  (f16)
    mma_gemm<EPI_SILU_AUX_MUL, true><<<dim3(INTER / 128, GY), gblk, GEMM_SMEM>>>(
        h2h, wmup, nullptr, muh, nullptr, mgh, INTER, HIDDEN);

    // out = xres + mu @ w_mlp_down^T
    mma_gemm<EPI_RESADD, false><<<dim3(HIDDEN / 128, GY), gblk, GEMM_SMEM>>>(
        muh, wmdp, out, nullptr, xres, nullptr, HIDDEN, INTER);
}

// round 10
// speedup vs baseline: 2.7948x; 1.0387x over previous
#include <cuda_runtime.h>
#include <cuda_fp16.h>
#include <math.h>
#include <stdint.h>

// ---------------------------------------------------------------------------
// HawkBlock: fp16 mma.sync GEMMs, f32 accum (CTA 128x128, 4 warps @ 64x64,
// 3-stage mbarrier ring w/ lane0 empty-arrives, 2 CTAs/SM) + parallel scan.
// ---------------------------------------------------------------------------

#define NTOK   16384
#define HIDDEN 1024
#define DREC   2048
#define INTER  4096
#define TLEN   4096
#define NB     4

#define SCHUNK   64
#define NCHUNKS  (TLEN / SCHUNK)   // 64
#define NCHAN    (NB * DREC)       // 8192

typedef __half f16;

// ---- static scratch ----
__device__ f16   g_h   [(size_t)NTOK * HIDDEN];
__device__ f16   g_h2  [(size_t)NTOK * HIDDEN];
__device__ float g_xres[(size_t)NTOK * HIDDEN];
__device__ f16   g_xin [(size_t)NTOK * DREC];
__device__ f16   g_gate[(size_t)NTOK * DREC];
__device__ float g_a   [(size_t)NTOK * DREC];
__device__ f16   g_y   [(size_t)NTOK * DREC];
__device__ f16   g_mg  [(size_t)NTOK * INTER];
__device__ f16   g_mu  [(size_t)NTOK * INTER];
__device__ float g_csum [2 * NCHUNKS * NCHAN];
__device__ float g_carry[NCHUNKS * NCHAN];

// ---- fp16 weights ----
__device__ f16 g_wi [(size_t)DREC * HIDDEN];
__device__ f16 g_wg [(size_t)DREC * HIDDEN];
__device__ f16 g_wa [(size_t)DREC * DREC];
__device__ f16 g_wo [(size_t)HIDDEN * DREC];
__device__ f16 g_wmg[(size_t)INTER * HIDDEN];
__device__ f16 g_wmu[(size_t)INTER * HIDDEN];
__device__ f16 g_wmd[(size_t)HIDDEN * INTER];

// ---------------------------------------------------------------------------
// helpers
// ---------------------------------------------------------------------------
__device__ __forceinline__ uint32_t smem_u32(const void* p) {
    uint32_t a;
    asm("{ .reg .u64 t; cvta.to.shared.u64 t, %1; cvt.u32.u64 %0, t; }"
        : "=r"(a) : "l"(p));
    return a;
}
__device__ __forceinline__ void cp16(uint32_t dst, const void* src) {
    asm volatile("cp.async.cg.shared.global [%0], [%1], 16;"
                 :: "r"(dst), "l"(src));
}
__device__ __forceinline__ void ldsm4(uint32_t (&r)[4], uint32_t addr) {
    asm volatile("ldmatrix.sync.aligned.m8n8.x4.shared.b16 {%0,%1,%2,%3}, [%4];"
                 : "=r"(r[0]), "=r"(r[1]), "=r"(r[2]), "=r"(r[3]) : "r"(addr));
}
__device__ __forceinline__ void mma_f16(float (&d)[4], const uint32_t (&a)[4],
                                        uint32_t b0, uint32_t b1) {
    asm volatile("mma.sync.aligned.m16n8k16.row.col.f32.f16.f16.f32 "
                 "{%0,%1,%2,%3}, {%4,%5,%6,%7}, {%8,%9}, {%0,%1,%2,%3};"
                 : "+f"(d[0]), "+f"(d[1]), "+f"(d[2]), "+f"(d[3])
                 : "r"(a[0]), "r"(a[1]), "r"(a[2]), "r"(a[3]), "r"(b0), "r"(b1));
}
__device__ __forceinline__ uint32_t pack_h2(f16 a, f16 b) {
    __half2 t = __halves2half2(a, b);
    return *reinterpret_cast<uint32_t*>(&t);
}

// ---- mbarrier primitives ----
#define MBAR_INIT(addr, cnt) \
    asm volatile("mbarrier.init.shared.b64 [%0], %1;" \
                 :: "r"((uint32_t)(addr)), "r"((uint32_t)(cnt)) : "memory")
#define MBAR_ARRIVE(addr) \
    asm volatile("mbarrier.arrive.shared.b64 _, [%0];" \
                 :: "r"((uint32_t)(addr)) : "memory")
#define CP_MBAR_ARRIVE(addr) \
    asm volatile("cp.async.mbarrier.arrive.noinc.shared.b64 [%0];" \
                 :: "r"((uint32_t)(addr)) : "memory")
#define MBAR_WAIT(addr, parity) do {                                            \
    uint32_t _m = (uint32_t)(addr); uint32_t _p = (uint32_t)(parity);           \
    uint32_t _d;                                                                \
    asm volatile("{\n\t.reg .pred p;\n\t"                                       \
        "mbarrier.try_wait.parity.acquire.cta.shared::cta.b64 p, [%1], %2;\n\t" \
        "selp.b32 %0, 1, 0, p;\n\t}" : "=r"(_d) : "r"(_m), "r"(_p) : "memory"); \
    if (!_d) {                                                                  \
        asm volatile("{\n\t.reg .pred P1;\n\t"                                  \
            "W_%=:\n\t"                                                         \
            "mbarrier.try_wait.parity.acquire.cta.shared::cta.b64 P1, [%0], %1, 0x989680;\n\t" \
            "@P1 bra.uni D_%=;\n\t"                                             \
            "bra.uni W_%=;\n\t"                                                 \
            "D_%=:\n\t}" :: "r"(_m), "r"(_p) : "memory");                       \
    }                                                                           \
} while (0)

// ---------------------------------------------------------------------------
// batched weight convert fp32 -> fp16 (7 arrays, one launch)
// ---------------------------------------------------------------------------
__global__ __launch_bounds__(256) void conv7(
    const float* __restrict__ s0, f16* __restrict__ d0, int n0,
    const float* __restrict__ s1, f16* __restrict__ d1, int n1,
    const float* __restrict__ s2, f16* __restrict__ d2, int n2,
    const float* __restrict__ s3, f16* __restrict__ d3, int n3,
    const float* __restrict__ s4, f16* __restrict__ d4, int n4,
    const float* __restrict__ s5, f16* __restrict__ d5, int n5,
    const float* __restrict__ s6, f16* __restrict__ d6, int n6)
{
    int j = blockIdx.x * 256 + threadIdx.x;
    const float* s; f16* d;
    if (j < n0) { s = s0; d = d0; }
    else { j -= n0;
    if (j < n1) { s = s1; d = d1; }
    else { j -= n1;
    if (j < n2) { s = s2; d = d2; }
    else { j -= n2;
    if (j < n3) { s = s3; d = d3; }
    else { j -= n3;
    if (j < n4) { s = s4; d = d4; }
    else { j -= n4;
    if (j < n5) { s = s5; d = d5; }
    else { j -= n5;
    if (j >= n6) return;
    s = s6; d = d6; }}}}}}
    float4 v = reinterpret_cast<const float4*>(s)[j];
    reinterpret_cast<uint2*>(d)[j] = make_uint2(
        pack_h2(__float2half(v.x), __float2half(v.y)),
        pack_h2(__float2half(v.z), __float2half(v.w)));
}

// ---------------------------------------------------------------------------
// RMSNorm -> fp16
// ---------------------------------------------------------------------------
__global__ __launch_bounds__(256) void rmsnorm_h16(
    const float* __restrict__ x, const float* __restrict__ w,
    f16* __restrict__ o)
{
    int tkn = blockIdx.x;
    int t = threadIdx.x;
    float4 v = reinterpret_cast<const float4*>(x + (size_t)tkn * HIDDEN)[t];
    float s = v.x * v.x + v.y * v.y + v.z * v.z + v.w * v.w;
    #pragma unroll
    for (int o2 = 16; o2 > 0; o2 >>= 1) s += __shfl_xor_sync(0xFFFFFFFFu, s, o2);
    __shared__ float ws[8];
    __shared__ float tot_sh;
    if ((t & 31) == 0) ws[t >> 5] = s;
    __syncthreads();
    if (t < 32) {
        float z = (t < 8) ? ws[t] : 0.0f;
        #pragma unroll
        for (int o2 = 4; o2 > 0; o2 >>= 1) z += __shfl_xor_sync(0xFFFFFFFFu, z, o2);
        if (t == 0) tot_sh = z;
    }
    __syncthreads();
    float r = rsqrtf(tot_sh * (1.0f / HIDDEN) + 1e-6f);
    float4 wv = reinterpret_cast<const float4*>(w)[t];
    size_t q = (size_t)tkn * (HIDDEN / 4) + t;
    reinterpret_cast<uint2*>(o)[q] = make_uint2(
        pack_h2(__float2half(v.x * r * wv.x), __float2half(v.y * r * wv.y)),
        pack_h2(__float2half(v.z * r * wv.z), __float2half(v.w * r * wv.w)));
}

// ---------------------------------------------------------------------------
// GEMM: C[N=16384, M] = A[N,K] @ W[M,K]^T, fp16 in, fp32 accum.
// CTA 128x128, 4 warps (64x64 warp tiles), BK=64, 3-stage mbarrier ring.
// Empty barriers: count 4, lane0-only arrives (ldmatrix is warp-sync, and
// arrive carries release semantics over the warp's prior smem reads).
// ---------------------------------------------------------------------------
#define EPI_NONE          0
#define EPI_SIGMOID       1
#define EPI_BIAS_SIGMOID  2
#define EPI_RESADD        3
#define EPI_SILU_AUX_MUL  4   // auxh = mg (f16)

template<int EPI>
__device__ __forceinline__ float epi_apply(float v,
                                           const float* __restrict__ auxf,
                                           const f16* __restrict__ auxh,
                                           size_t idx, int col)
{
    if (EPI == EPI_SIGMOID)      return 1.0f / (1.0f + expf(-v));
    if (EPI == EPI_BIAS_SIGMOID) { float z = v + __ldg(&auxf[col]);
                                   return 1.0f / (1.0f + expf(-z)); }
    if (EPI == EPI_RESADD)       return v + __ldg(&auxf[idx]);
    if (EPI == EPI_SILU_AUX_MUL) { float g = __half2float(__ldg(&auxh[idx]));
                                   return v * (g / (1.0f + expf(-g))); }
    return v;
}

#define STAGE_B   32768u
#define GEMM_SMEM (3 * 32768 + 64)

template<int EPI, bool OUT16>
__global__ __launch_bounds__(128, 2) void mma_gemm(
    const f16* __restrict__ A, const f16* __restrict__ B,
    float* __restrict__ Cf, f16* __restrict__ Ch,
    const float* __restrict__ auxf, const f16* __restrict__ auxh,
    int M, int K)
{
    extern __shared__ char smem[];
    const uint32_t sb = smem_u32(smem);
    const uint32_t mb = sb + 3u * STAGE_B;       // full[s]=mb+8s, empty[s]=mb+24+8s
    const int tid = threadIdx.x;
    const int lane = tid & 31;
    const int wid = tid >> 5;
    const int warp_m = wid >> 1;    // 0..1
    const int warp_n = wid & 1;     // 0..1
    const int rowBlock = blockIdx.y * 128;
    const int colBlock = blockIdx.x * 128;
    const int nch = K >> 6;

    const f16* gpA = A + (size_t)rowBlock * K;
    const f16* gpB = B + (size_t)colBlock * K;

    if (tid == 0) {
        #pragma unroll
        for (int s = 0; s < 3; s++) {
            MBAR_INIT(mb + s * 8, 128);        // full: 128 cp.async arrivals
            MBAR_INIT(mb + 24 + s * 8, 4);     // empty: 4 lane0 arrivals
        }
    }
    __syncthreads();

    auto issue = [&](int c, int buf) {
        const int kb = c * 64;
        uint32_t st = sb + (uint32_t)buf * STAGE_B;
        #pragma unroll
        for (int i = 0; i < 8; i++) {
            int u = tid + i * 128;
            int r = u >> 3, cc = u & 7;
            cp16(st + r * 128 + ((cc ^ (r & 7)) << 4),
                 gpA + (size_t)r * K + kb + cc * 8);
        }
        #pragma unroll
        for (int i = 0; i < 8; i++) {
            int u = tid + i * 128;
            int r = u >> 3, cc = u & 7;
            cp16(st + 16384u + r * 128 + ((cc ^ (r & 7)) << 4),
                 gpB + (size_t)r * K + kb + cc * 8);
        }
    };

    float acc[4][8][4];
    #pragma unroll
    for (int i = 0; i < 4; i++)
        #pragma unroll
        for (int j = 0; j < 8; j++)
            #pragma unroll
            for (int k = 0; k < 4; k++) acc[i][j][k] = 0.0f;

    // producer cursor (phase starts 1: first empty-wait passes on fresh barrier)
    int pstage = 0, pphase = 1;
    // consumer cursor
    int cstage = 0, cphase = 0;

    // prologue: fill all 3 stages
    #pragma unroll
    for (int s = 0; s < 3; s++) {
        if (s < nch) {
            MBAR_WAIT(mb + 24 + pstage * 8, pphase);
            issue(s, pstage);
            CP_MBAR_ARRIVE(mb + pstage * 8);
            pstage++; if (pstage == 3) { pstage = 0; pphase ^= 1; }
        }
    }

    // lane-level ldmatrix addressing (row&7 == lane&7)
    const int aRow0 = warp_m * 64 + (lane & 7) + ((lane >> 3) & 1) * 8;
    const int aKh   = (lane >> 4) & 1;
    const int bRow0 = warp_n * 64 + ((lane >> 4) & 1) * 8 + (lane & 7);
    const int bKh   = (lane >> 3) & 1;
    const int swz   = lane & 7;

    for (int c = 0; c < nch; c++) {
        int s = cstage;
        MBAR_WAIT(mb + s * 8, cphase);
        cstage++; if (cstage == 3) { cstage = 0; cphase ^= 1; }

        uint32_t st = sb + (uint32_t)s * STAGE_B;
        #pragma unroll
        for (int ks = 0; ks < 4; ks++) {
            uint32_t afr[4][4];
            #pragma unroll
            for (int mt = 0; mt < 4; mt++) {
                uint32_t roff = (uint32_t)(aRow0 + mt * 16) * 128
                              + (uint32_t)(((ks * 2 + aKh) ^ swz) << 4);
                ldsm4(afr[mt], st + roff);
            }
            uint32_t bfr[8][2];
            #pragma unroll
            for (int p = 0; p < 4; p++) {
                uint32_t roff = (uint32_t)(bRow0 + p * 16) * 128
                              + (uint32_t)(((ks * 2 + bKh) ^ swz) << 4);
                uint32_t t4[4];
                ldsm4(t4, st + 16384u + roff);
                bfr[2 * p][0] = t4[0]; bfr[2 * p][1] = t4[1];
                bfr[2 * p + 1][0] = t4[2]; bfr[2 * p + 1][1] = t4[3];
            }
            #pragma unroll
            for (int mt = 0; mt < 4; mt++)
                #pragma unroll
                for (int nt = 0; nt < 8; nt++)
                    mma_f16(acc[mt][nt], afr[mt], bfr[nt][0], bfr[nt][1]);
        }

        if (lane == 0) MBAR_ARRIVE(mb + 24 + s * 8);  // warp done reading stage s

        if (c + 3 < nch) {
            MBAR_WAIT(mb + 24 + pstage * 8, pphase);   // stage fully drained
            issue(c + 3, pstage);
            CP_MBAR_ARRIVE(mb + pstage * 8);
            pstage++; if (pstage == 3) { pstage = 0; pphase ^= 1; }
        }
    }

    // epilogue (per-warp independent)
    #pragma unroll
    for (int mt = 0; mt < 4; mt++) {
        #pragma unroll
        for (int nt = 0; nt < 8; nt++) {
            int col = colBlock + warp_n * 64 + nt * 8 + (lane & 3) * 2;
            #pragma unroll
            for (int half = 0; half < 2; half++) {
                int row = rowBlock + warp_m * 64 + mt * 16 + (lane >> 2) + half * 8;
                size_t idx = (size_t)row * M + col;
                float f0 = epi_apply<EPI>(acc[mt][nt][half * 2 + 0], auxf, auxh, idx, col);
                float f1 = epi_apply<EPI>(acc[mt][nt][half * 2 + 1], auxf, auxh, idx + 1, col + 1);
                if (OUT16) {
                    *reinterpret_cast<uint32_t*>(Ch + idx) =
                        pack_h2(__float2half(f0), __float2half(f1));
                } else {
                    *reinterpret_cast<float2*>(Cf + idx) = make_float2(f0, f1);
                }
            }
        }
    }
}

// ---------------------------------------------------------------------------
// Parallel Hawk scan, recompute style
// ---------------------------------------------------------------------------
__global__ __launch_bounds__(256) void scan_part1(
    const f16* __restrict__ xin, const float* __restrict__ a,
    float* __restrict__ csum)
{
    int id = blockIdx.x * 256 + threadIdx.x;
    int chunk = id >> 13;
    int chp = id & (NCHAN - 1);
    int b = chp >> 11;
    int d = chp & (DREC - 1);
    size_t base = ((size_t)b * TLEN + (size_t)chunk * SCHUNK) * DREC + d;

    float h = 0.0f, Aacc = 1.0f;
    #pragma unroll 4
    for (int t = 0; t < SCHUNK; t++) {
        size_t idx = base + (size_t)t * DREC;
        float at = __ldg(&a[idx]);
        float xt = __half2float(__ldg(&xin[idx]));
        float s = sqrtf(fmaf(-at, at, 1.0f) + 1e-8f);
        h = fmaf(at, h, s * xt);
        Aacc *= at;
    }
    csum[(size_t)chunk * NCHAN + chp] = Aacc;
    csum[(size_t)NCHUNKS * NCHAN + (size_t)chunk * NCHAN + chp] = h;
}

__global__ __launch_bounds__(256) void scan_part2(
    const float* __restrict__ csum, float* __restrict__ carry)
{
    int chp = blockIdx.x * 256 + threadIdx.x;
    float h = 0.0f;
    #pragma unroll 8
    for (int c = 0; c < NCHUNKS; c++) {
        carry[(size_t)c * NCHAN + chp] = h;
        float Ac = csum[(size_t)c * NCHAN + chp];
        float hc = csum[(size_t)NCHUNKS * NCHAN + (size_t)c * NCHAN + chp];
        h = fmaf(Ac, h, hc);
    }
}

__global__ __launch_bounds__(256) void scan_part3(
    const f16* __restrict__ xin, const float* __restrict__ a,
    const f16* __restrict__ gate, const float* __restrict__ carry,
    f16* __restrict__ y)
{
    int id = blockIdx.x * 256 + threadIdx.x;
    int chunk = id >> 13;
    int chp = id & (NCHAN - 1);
    int b = chp >> 11;
    int d = chp & (DREC - 1);
    size_t base = ((size_t)b * TLEN + (size_t)chunk * SCHUNK) * DREC + d;

    float h = __ldg(&carry[(size_t)chunk * NCHAN + chp]);
    #pragma unroll 4
    for (int t = 0; t < SCHUNK; t++) {
        size_t idx = base + (size_t)t * DREC;
        float at = __ldg(&a[idx]);
        float xt = __half2float(__ldg(&xin[idx]));
        float gt = __half2float(__ldg(&gate[idx]));
        float s = sqrtf(fmaf(-at, at, 1.0f) + 1e-8f);
        h = fmaf(at, h, s * xt);
        y[idx] = __float2half(gt * h);
    }
}

// ---------------------------------------------------------------------------
// Launch
// ---------------------------------------------------------------------------
#define SYM(p, s) cudaGetSymbolAddress((void**)&p, s)

extern "C" void kernel_launch(void* const* d_in, const int* in_sizes, int n_in,
                              void* d_out, int out_size)
{
    const float* x       = (const float*)d_in[0];
    const float* ln1_w   = (const float*)d_in[1];
    const float* ln2_w   = (const float*)d_in[2];
    const float* w_in    = (const float*)d_in[3];
    const float* w_gate  = (const float*)d_in[4];
    const float* a_param = (const float*)d_in[5];
    const float* w_a     = (const float*)d_in[6];
    const float* w_out   = (const float*)d_in[7];
    const float* w_mg    = (const float*)d_in[8];
    const float* w_mu    = (const float*)d_in[9];
    const float* w_md    = (const float*)d_in[10];
    float* out = (float*)d_out;

    f16 *hh, *h2h, *xinh, *gateh, *yh, *mgh, *muh;
    float *xres, *aa, *csum, *carry;
    f16 *wi, *wg, *wa, *wo, *wmgp, *wmup, *wmdp;

    SYM(hh, g_h);     SYM(h2h, g_h2);
    SYM(xinh, g_xin); SYM(gateh, g_gate);
    SYM(yh, g_y);     SYM(mgh, g_mg);    SYM(muh, g_mu);
    SYM(xres, g_xres); SYM(aa, g_a);
    SYM(csum, g_csum); SYM(carry, g_carry);
    SYM(wi, g_wi);  SYM(wg, g_wg);  SYM(wa, g_wa);  SYM(wo, g_wo);
    SYM(wmgp, g_wmg); SYM(wmup, g_wmu); SYM(wmdp, g_wmd);

    cudaFuncSetAttribute(mma_gemm<EPI_NONE, true>,          cudaFuncAttributeMaxDynamicSharedMemorySize, GEMM_SMEM);
    cudaFuncSetAttribute(mma_gemm<EPI_SIGMOID, true>,       cudaFuncAttributeMaxDynamicSharedMemorySize, GEMM_SMEM);
    cudaFuncSetAttribute(mma_gemm<EPI_BIAS_SIGMOID, false>, cudaFuncAttributeMaxDynamicSharedMemorySize, GEMM_SMEM);
    cudaFuncSetAttribute(mma_gemm<EPI_RESADD, false>,       cudaFuncAttributeMaxDynamicSharedMemorySize, GEMM_SMEM);
    cudaFuncSetAttribute(mma_gemm<EPI_SILU_AUX_MUL, true>,  cudaFuncAttributeMaxDynamicSharedMemorySize, GEMM_SMEM);

    dim3 blk(256);
    dim3 gblk(128);
    const int GY = NTOK / 128;   // 128

    const int n_ih = DREC * HIDDEN / 4;   // 524288
    const int n_aa = DREC * DREC / 4;     // 1048576
    const int n_mh = INTER * HIDDEN / 4;  // 1048576

    // launch 0: convert all 7 weights to fp16
    {
        int total = 3 * n_ih + n_aa + 3 * n_mh;
        conv7<<<(total + 255) / 256, blk>>>(
            w_in, wi, n_ih,
            w_gate, wg, n_ih,
            w_a, wa, n_aa,
            w_out, wo, n_ih,
            w_mg, wmgp, n_mh,
            w_mu, wmup, n_mh,
            w_md, wmdp, n_mh);
    }

    // launch 1: h = rmsnorm(x, ln1)
    rmsnorm_h16<<<NTOK, blk>>>(x, ln1_w, hh);

    // launch 2: xin = h @ w_in^T
    mma_gemm<EPI_NONE, true><<<dim3(DREC / 128, GY), gblk, GEMM_SMEM>>>(
        hh, wi, nullptr, xinh, nullptr, nullptr, DREC, HIDDEN);

    // launch 3: gate = sigmoid(h @ w_gate^T)  (f16)
    mma_gemm<EPI_SIGMOID, true><<<dim3(DREC / 128, GY), gblk, GEMM_SMEM>>>(
        hh, wg, nullptr, gateh, nullptr, nullptr, DREC, HIDDEN);

    // launch 4: a = sigmoid(a_param + xin @ w_a^T)  (f32)
    mma_gemm<EPI_BIAS_SIGMOID, false><<<dim3(DREC / 128, GY), gblk, GEMM_SMEM>>>(
        xinh, wa, aa, nullptr, a_param, nullptr, DREC, DREC);

    // launch 5 (ncu profiles this): scan part1
    scan_part1<<<(NCHUNKS * NCHAN) / 256, blk>>>(xinh, aa, csum);
    scan_part2<<<NCHAN / 256, blk>>>(csum, carry);
    scan_part3<<<(NCHUNKS * NCHAN) / 256, blk>>>(xinh, aa, gateh, carry, yh);

    // xres = x + y @ w_out^T
    mma_gemm<EPI_RESADD, false><<<dim3(HIDDEN / 128, GY), gblk, GEMM_SMEM>>>(
        yh, wo, xres, nullptr, x, nullptr, HIDDEN, DREC);

    // h2 = rmsnorm(xres, ln2)
    rmsnorm_h16<<<NTOK, blk>>>(xres, ln2_w, h2h);

    // mg = h2 @ w_mlp_gate^T  (f16)
    mma_gemm<EPI_NONE, true><<<dim3(INTER / 128, GY), gblk, GEMM_SMEM>>>(
        h2h, wmgp, nullptr, mgh, nullptr, nullptr, INTER, HIDDEN);

    // mu = silu(mg) * (h2 @ w_mlp_up^T)  (f16)
    mma_gemm<EPI_SILU_AUX_MUL, true><<<dim3(INTER / 128, GY), gblk, GEMM_SMEM>>>(
        h2h, wmup, nullptr, muh, nullptr, mgh, INTER, HIDDEN);

    // out = xres + mu @ w_mlp_down^T
    mma_gemm<EPI_RESADD, false><<<dim3(HIDDEN / 128, GY), gblk, GEMM_SMEM>>>(
        muh, wmdp, out, nullptr, xres, nullptr, HIDDEN, INTER);
}

// round 11
// speedup vs baseline: 3.2451x; 1.1611x over previous
#include <cuda_runtime.h>
#include <cuda_fp16.h>
#include <math.h>
#include <stdint.h>

// ---------------------------------------------------------------------------
// HawkBlock: fp16 mma.sync GEMMs, f32 accum, 3-stage mbarrier ring,
// fused dual-B MLP (gate+up -> silu fused), fast-math epilogues,
// recompute-style parallel scan.
// ---------------------------------------------------------------------------

#define NTOK   16384
#define HIDDEN 1024
#define DREC   2048
#define INTER  4096
#define TLEN   4096
#define NB     4

#define SCHUNK   64
#define NCHUNKS  (TLEN / SCHUNK)   // 64
#define NCHAN    (NB * DREC)       // 8192

typedef __half f16;

// ---- static scratch ----
__device__ f16   g_h   [(size_t)NTOK * HIDDEN];
__device__ f16   g_h2  [(size_t)NTOK * HIDDEN];
__device__ float g_xres[(size_t)NTOK * HIDDEN];
__device__ f16   g_xin [(size_t)NTOK * DREC];
__device__ f16   g_gate[(size_t)NTOK * DREC];
__device__ float g_a   [(size_t)NTOK * DREC];
__device__ f16   g_y   [(size_t)NTOK * DREC];
__device__ f16   g_mu  [(size_t)NTOK * INTER];
__device__ float g_csum [2 * NCHUNKS * NCHAN];
__device__ float g_carry[NCHUNKS * NCHAN];

// ---- fp16 weights ----
__device__ f16 g_wi [(size_t)DREC * HIDDEN];
__device__ f16 g_wg [(size_t)DREC * HIDDEN];
__device__ f16 g_wa [(size_t)DREC * DREC];
__device__ f16 g_wo [(size_t)HIDDEN * DREC];
__device__ f16 g_wmg[(size_t)INTER * HIDDEN];
__device__ f16 g_wmu[(size_t)INTER * HIDDEN];
__device__ f16 g_wmd[(size_t)HIDDEN * INTER];

// ---------------------------------------------------------------------------
// helpers
// ---------------------------------------------------------------------------
__device__ __forceinline__ uint32_t smem_u32(const void* p) {
    uint32_t a;
    asm("{ .reg .u64 t; cvta.to.shared.u64 t, %1; cvt.u32.u64 %0, t; }"
        : "=r"(a) : "l"(p));
    return a;
}
__device__ __forceinline__ void cp16(uint32_t dst, const void* src) {
    asm volatile("cp.async.cg.shared.global [%0], [%1], 16;"
                 :: "r"(dst), "l"(src));
}
__device__ __forceinline__ void ldsm4(uint32_t (&r)[4], uint32_t addr) {
    asm volatile("ldmatrix.sync.aligned.m8n8.x4.shared.b16 {%0,%1,%2,%3}, [%4];"
                 : "=r"(r[0]), "=r"(r[1]), "=r"(r[2]), "=r"(r[3]) : "r"(addr));
}
__device__ __forceinline__ void mma_f16(float (&d)[4], const uint32_t (&a)[4],
                                        uint32_t b0, uint32_t b1) {
    asm volatile("mma.sync.aligned.m16n8k16.row.col.f32.f16.f16.f32 "
                 "{%0,%1,%2,%3}, {%4,%5,%6,%7}, {%8,%9}, {%0,%1,%2,%3};"
                 : "+f"(d[0]), "+f"(d[1]), "+f"(d[2]), "+f"(d[3])
                 : "r"(a[0]), "r"(a[1]), "r"(a[2]), "r"(a[3]), "r"(b0), "r"(b1));
}
__device__ __forceinline__ uint32_t pack_h2(f16 a, f16 b) {
    __half2 t = __halves2half2(a, b);
    return *reinterpret_cast<uint32_t*>(&t);
}
__device__ __forceinline__ float fast_sig(float v) {
    return __fdividef(1.0f, 1.0f + __expf(-v));
}

// ---- mbarrier primitives ----
#define MBAR_INIT(addr, cnt) \
    asm volatile("mbarrier.init.shared.b64 [%0], %1;" \
                 :: "r"((uint32_t)(addr)), "r"((uint32_t)(cnt)) : "memory")
#define MBAR_ARRIVE(addr) \
    asm volatile("mbarrier.arrive.shared.b64 _, [%0];" \
                 :: "r"((uint32_t)(addr)) : "memory")
#define CP_MBAR_ARRIVE(addr) \
    asm volatile("cp.async.mbarrier.arrive.noinc.shared.b64 [%0];" \
                 :: "r"((uint32_t)(addr)) : "memory")
#define MBAR_WAIT(addr, parity) do {                                            \
    uint32_t _m = (uint32_t)(addr); uint32_t _p = (uint32_t)(parity);           \
    uint32_t _d;                                                                \
    asm volatile("{\n\t.reg .pred p;\n\t"                                       \
        "mbarrier.try_wait.parity.acquire.cta.shared::cta.b64 p, [%1], %2;\n\t" \
        "selp.b32 %0, 1, 0, p;\n\t}" : "=r"(_d) : "r"(_m), "r"(_p) : "memory"); \
    if (!_d) {                                                                  \
        asm volatile("{\n\t.reg .pred P1;\n\t"                                  \
            "W_%=:\n\t"                                                         \
            "mbarrier.try_wait.parity.acquire.cta.shared::cta.b64 P1, [%0], %1, 0x989680;\n\t" \
            "@P1 bra.uni D_%=;\n\t"                                             \
            "bra.uni W_%=;\n\t"                                                 \
            "D_%=:\n\t}" :: "r"(_m), "r"(_p) : "memory");                       \
    }                                                                           \
} while (0)

// ---------------------------------------------------------------------------
// batched weight convert fp32 -> fp16 (7 arrays, one launch)
// ---------------------------------------------------------------------------
__global__ __launch_bounds__(256) void conv7(
    const float* __restrict__ s0, f16* __restrict__ d0, int n0,
    const float* __restrict__ s1, f16* __restrict__ d1, int n1,
    const float* __restrict__ s2, f16* __restrict__ d2, int n2,
    const float* __restrict__ s3, f16* __restrict__ d3, int n3,
    const float* __restrict__ s4, f16* __restrict__ d4, int n4,
    const float* __restrict__ s5, f16* __restrict__ d5, int n5,
    const float* __restrict__ s6, f16* __restrict__ d6, int n6)
{
    int j = blockIdx.x * 256 + threadIdx.x;
    const float* s; f16* d;
    if (j < n0) { s = s0; d = d0; }
    else { j -= n0;
    if (j < n1) { s = s1; d = d1; }
    else { j -= n1;
    if (j < n2) { s = s2; d = d2; }
    else { j -= n2;
    if (j < n3) { s = s3; d = d3; }
    else { j -= n3;
    if (j < n4) { s = s4; d = d4; }
    else { j -= n4;
    if (j < n5) { s = s5; d = d5; }
    else { j -= n5;
    if (j >= n6) return;
    s = s6; d = d6; }}}}}}
    float4 v = reinterpret_cast<const float4*>(s)[j];
    reinterpret_cast<uint2*>(d)[j] = make_uint2(
        pack_h2(__float2half(v.x), __float2half(v.y)),
        pack_h2(__float2half(v.z), __float2half(v.w)));
}

// ---------------------------------------------------------------------------
// RMSNorm -> fp16
// ---------------------------------------------------------------------------
__global__ __launch_bounds__(256) void rmsnorm_h16(
    const float* __restrict__ x, const float* __restrict__ w,
    f16* __restrict__ o)
{
    int tkn = blockIdx.x;
    int t = threadIdx.x;
    float4 v = reinterpret_cast<const float4*>(x + (size_t)tkn * HIDDEN)[t];
    float s = v.x * v.x + v.y * v.y + v.z * v.z + v.w * v.w;
    #pragma unroll
    for (int o2 = 16; o2 > 0; o2 >>= 1) s += __shfl_xor_sync(0xFFFFFFFFu, s, o2);
    __shared__ float ws[8];
    __shared__ float tot_sh;
    if ((t & 31) == 0) ws[t >> 5] = s;
    __syncthreads();
    if (t < 32) {
        float z = (t < 8) ? ws[t] : 0.0f;
        #pragma unroll
        for (int o2 = 4; o2 > 0; o2 >>= 1) z += __shfl_xor_sync(0xFFFFFFFFu, z, o2);
        if (t == 0) tot_sh = z;
    }
    __syncthreads();
    float r = rsqrtf(tot_sh * (1.0f / HIDDEN) + 1e-6f);
    float4 wv = reinterpret_cast<const float4*>(w)[t];
    size_t q = (size_t)tkn * (HIDDEN / 4) + t;
    reinterpret_cast<uint2*>(o)[q] = make_uint2(
        pack_h2(__float2half(v.x * r * wv.x), __float2half(v.y * r * wv.y)),
        pack_h2(__float2half(v.z * r * wv.z), __float2half(v.w * r * wv.w)));
}

// ---------------------------------------------------------------------------
// Single-B GEMM (CTA 128x128, 4 warps @ 64x64, 3-stage mbarrier ring)
// ---------------------------------------------------------------------------
#define EPI_NONE          0
#define EPI_SIGMOID       1
#define EPI_BIAS_SIGMOID  2
#define EPI_RESADD        3

template<int EPI>
__device__ __forceinline__ float epi_apply(float v,
                                           const float* __restrict__ auxf,
                                           size_t idx, int col)
{
    if (EPI == EPI_SIGMOID)      return fast_sig(v);
    if (EPI == EPI_BIAS_SIGMOID) return fast_sig(v + __ldg(&auxf[col]));
    if (EPI == EPI_RESADD)       return v + __ldg(&auxf[idx]);
    return v;
}

#define STAGE_B   32768u
#define GEMM_SMEM (3 * 32768 + 64)

template<int EPI, bool OUT16>
__global__ __launch_bounds__(128, 2) void mma_gemm(
    const f16* __restrict__ A, const f16* __restrict__ B,
    float* __restrict__ Cf, f16* __restrict__ Ch,
    const float* __restrict__ auxf, int M, int K)
{
    extern __shared__ char smem[];
    const uint32_t sb = smem_u32(smem);
    const uint32_t mb = sb + 3u * STAGE_B;
    const int tid = threadIdx.x;
    const int lane = tid & 31;
    const int wid = tid >> 5;
    const int warp_m = wid >> 1;
    const int warp_n = wid & 1;
    const int rowBlock = blockIdx.y * 128;
    const int colBlock = blockIdx.x * 128;
    const int nch = K >> 6;

    const f16* gpA = A + (size_t)rowBlock * K;
    const f16* gpB = B + (size_t)colBlock * K;

    if (tid == 0) {
        #pragma unroll
        for (int s = 0; s < 3; s++) {
            MBAR_INIT(mb + s * 8, 128);
            MBAR_INIT(mb + 24 + s * 8, 4);
        }
    }
    __syncthreads();

    auto issue = [&](int c, int buf) {
        const int kb = c * 64;
        uint32_t st = sb + (uint32_t)buf * STAGE_B;
        #pragma unroll
        for (int i = 0; i < 8; i++) {
            int u = tid + i * 128;
            int r = u >> 3, cc = u & 7;
            cp16(st + r * 128 + ((cc ^ (r & 7)) << 4),
                 gpA + (size_t)r * K + kb + cc * 8);
        }
        #pragma unroll
        for (int i = 0; i < 8; i++) {
            int u = tid + i * 128;
            int r = u >> 3, cc = u & 7;
            cp16(st + 16384u + r * 128 + ((cc ^ (r & 7)) << 4),
                 gpB + (size_t)r * K + kb + cc * 8);
        }
    };

    float acc[4][8][4];
    #pragma unroll
    for (int i = 0; i < 4; i++)
        #pragma unroll
        for (int j = 0; j < 8; j++)
            #pragma unroll
            for (int k = 0; k < 4; k++) acc[i][j][k] = 0.0f;

    int pstage = 0, pphase = 1;
    int cstage = 0, cphase = 0;

    #pragma unroll
    for (int s = 0; s < 3; s++) {
        if (s < nch) {
            MBAR_WAIT(mb + 24 + pstage * 8, pphase);
            issue(s, pstage);
            CP_MBAR_ARRIVE(mb + pstage * 8);
            pstage++; if (pstage == 3) { pstage = 0; pphase ^= 1; }
        }
    }

    const int aRow0 = warp_m * 64 + (lane & 7) + ((lane >> 3) & 1) * 8;
    const int aKh   = (lane >> 4) & 1;
    const int bRow0 = warp_n * 64 + ((lane >> 4) & 1) * 8 + (lane & 7);
    const int bKh   = (lane >> 3) & 1;
    const int swz   = lane & 7;

    for (int c = 0; c < nch; c++) {
        int s = cstage;
        MBAR_WAIT(mb + s * 8, cphase);
        cstage++; if (cstage == 3) { cstage = 0; cphase ^= 1; }

        uint32_t st = sb + (uint32_t)s * STAGE_B;
        #pragma unroll
        for (int ks = 0; ks < 4; ks++) {
            uint32_t afr[4][4];
            #pragma unroll
            for (int mt = 0; mt < 4; mt++) {
                uint32_t roff = (uint32_t)(aRow0 + mt * 16) * 128
                              + (uint32_t)(((ks * 2 + aKh) ^ swz) << 4);
                ldsm4(afr[mt], st + roff);
            }
            uint32_t bfr[8][2];
            #pragma unroll
            for (int p = 0; p < 4; p++) {
                uint32_t roff = (uint32_t)(bRow0 + p * 16) * 128
                              + (uint32_t)(((ks * 2 + bKh) ^ swz) << 4);
                uint32_t t4[4];
                ldsm4(t4, st + 16384u + roff);
                bfr[2 * p][0] = t4[0]; bfr[2 * p][1] = t4[1];
                bfr[2 * p + 1][0] = t4[2]; bfr[2 * p + 1][1] = t4[3];
            }
            #pragma unroll
            for (int mt = 0; mt < 4; mt++)
                #pragma unroll
                for (int nt = 0; nt < 8; nt++)
                    mma_f16(acc[mt][nt], afr[mt], bfr[nt][0], bfr[nt][1]);
        }

        if (lane == 0) MBAR_ARRIVE(mb + 24 + s * 8);

        if (c + 3 < nch) {
            MBAR_WAIT(mb + 24 + pstage * 8, pphase);
            issue(c + 3, pstage);
            CP_MBAR_ARRIVE(mb + pstage * 8);
            pstage++; if (pstage == 3) { pstage = 0; pphase ^= 1; }
        }
    }

    #pragma unroll
    for (int mt = 0; mt < 4; mt++) {
        #pragma unroll
        for (int nt = 0; nt < 8; nt++) {
            int col = colBlock + warp_n * 64 + nt * 8 + (lane & 3) * 2;
            #pragma unroll
            for (int half = 0; half < 2; half++) {
                int row = rowBlock + warp_m * 64 + mt * 16 + (lane >> 2) + half * 8;
                size_t idx = (size_t)row * M + col;
                float f0 = epi_apply<EPI>(acc[mt][nt][half * 2 + 0], auxf, idx, col);
                float f1 = epi_apply<EPI>(acc[mt][nt][half * 2 + 1], auxf, idx + 1, col + 1);
                if (OUT16) {
                    *reinterpret_cast<uint32_t*>(Ch + idx) =
                        pack_h2(__float2half(f0), __float2half(f1));
                } else {
                    *reinterpret_cast<float2*>(Cf + idx) = make_float2(f0, f1);
                }
            }
        }
    }
}

// ---------------------------------------------------------------------------
// Dual-B GEMM for MLP: mu = silu(A@B1^T) * (A@B2^T), fused.
// CTA 128 rows x 64 cols, 4 warps (64x32 warp tiles per matrix).
// Stage = A 16KB + B1 8KB + B2 8KB = 32KB, same 3-stage ring.
// ---------------------------------------------------------------------------
__global__ __launch_bounds__(128, 2) void mma_gemm_dual(
    const f16* __restrict__ A, const f16* __restrict__ B1,
    const f16* __restrict__ B2, f16* __restrict__ Ch,
    int M, int K)
{
    extern __shared__ char smem[];
    const uint32_t sb = smem_u32(smem);
    const uint32_t mb = sb + 3u * STAGE_B;
    const int tid = threadIdx.x;
    const int lane = tid & 31;
    const int wid = tid >> 5;
    const int warp_m = wid >> 1;    // 0..1 (64 rows)
    const int warp_n = wid & 1;     // 0..1 (32 cols)
    const int rowBlock = blockIdx.y * 128;
    const int colBlock = blockIdx.x * 64;
    const int nch = K >> 6;

    const f16* gpA  = A  + (size_t)rowBlock * K;
    const f16* gpB1 = B1 + (size_t)colBlock * K;
    const f16* gpB2 = B2 + (size_t)colBlock * K;

    if (tid == 0) {
        #pragma unroll
        for (int s = 0; s < 3; s++) {
            MBAR_INIT(mb + s * 8, 128);
            MBAR_INIT(mb + 24 + s * 8, 4);
        }
    }
    __syncthreads();

    auto issue = [&](int c, int buf) {
        const int kb = c * 64;
        uint32_t st = sb + (uint32_t)buf * STAGE_B;
        #pragma unroll
        for (int i = 0; i < 8; i++) {          // A: 128x64
            int u = tid + i * 128;
            int r = u >> 3, cc = u & 7;
            cp16(st + r * 128 + ((cc ^ (r & 7)) << 4),
                 gpA + (size_t)r * K + kb + cc * 8);
        }
        #pragma unroll
        for (int i = 0; i < 4; i++) {          // B1: 64x64
            int u = tid + i * 128;
            int r = u >> 3, cc = u & 7;
            cp16(st + 16384u + r * 128 + ((cc ^ (r & 7)) << 4),
                 gpB1 + (size_t)r * K + kb + cc * 8);
        }
        #pragma unroll
        for (int i = 0; i < 4; i++) {          // B2: 64x64
            int u = tid + i * 128;
            int r = u >> 3, cc = u & 7;
            cp16(st + 24576u + r * 128 + ((cc ^ (r & 7)) << 4),
                 gpB2 + (size_t)r * K + kb + cc * 8);
        }
    };

    float acc1[4][4][4], acc2[4][4][4];
    #pragma unroll
    for (int i = 0; i < 4; i++)
        #pragma unroll
        for (int j = 0; j < 4; j++)
            #pragma unroll
            for (int k = 0; k < 4; k++) { acc1[i][j][k] = 0.0f; acc2[i][j][k] = 0.0f; }

    int pstage = 0, pphase = 1;
    int cstage = 0, cphase = 0;

    #pragma unroll
    for (int s = 0; s < 3; s++) {
        if (s < nch) {
            MBAR_WAIT(mb + 24 + pstage * 8, pphase);
            issue(s, pstage);
            CP_MBAR_ARRIVE(mb + pstage * 8);
            pstage++; if (pstage == 3) { pstage = 0; pphase ^= 1; }
        }
    }

    const int aRow0 = warp_m * 64 + (lane & 7) + ((lane >> 3) & 1) * 8;
    const int aKh   = (lane >> 4) & 1;
    const int bRow0 = warp_n * 32 + ((lane >> 4) & 1) * 8 + (lane & 7);
    const int bKh   = (lane >> 3) & 1;
    const int swz   = lane & 7;

    for (int c = 0; c < nch; c++) {
        int s = cstage;
        MBAR_WAIT(mb + s * 8, cphase);
        cstage++; if (cstage == 3) { cstage = 0; cphase ^= 1; }

        uint32_t st = sb + (uint32_t)s * STAGE_B;
        #pragma unroll
        for (int ks = 0; ks < 4; ks++) {
            uint32_t afr[4][4];
            #pragma unroll
            for (int mt = 0; mt < 4; mt++) {
                uint32_t roff = (uint32_t)(aRow0 + mt * 16) * 128
                              + (uint32_t)(((ks * 2 + aKh) ^ swz) << 4);
                ldsm4(afr[mt], st + roff);
            }
            uint32_t b1fr[4][2], b2fr[4][2];
            #pragma unroll
            for (int p = 0; p < 2; p++) {
                uint32_t roff = (uint32_t)(bRow0 + p * 16) * 128
                              + (uint32_t)(((ks * 2 + bKh) ^ swz) << 4);
                uint32_t t4[4];
                ldsm4(t4, st + 16384u + roff);
                b1fr[2 * p][0] = t4[0]; b1fr[2 * p][1] = t4[1];
                b1fr[2 * p + 1][0] = t4[2]; b1fr[2 * p + 1][1] = t4[3];
                ldsm4(t4, st + 24576u + roff);
                b2fr[2 * p][0] = t4[0]; b2fr[2 * p][1] = t4[1];
                b2fr[2 * p + 1][0] = t4[2]; b2fr[2 * p + 1][1] = t4[3];
            }
            #pragma unroll
            for (int mt = 0; mt < 4; mt++)
                #pragma unroll
                for (int nt = 0; nt < 4; nt++)
                    mma_f16(acc1[mt][nt], afr[mt], b1fr[nt][0], b1fr[nt][1]);
            #pragma unroll
            for (int mt = 0; mt < 4; mt++)
                #pragma unroll
                for (int nt = 0; nt < 4; nt++)
                    mma_f16(acc2[mt][nt], afr[mt], b2fr[nt][0], b2fr[nt][1]);
        }

        if (lane == 0) MBAR_ARRIVE(mb + 24 + s * 8);

        if (c + 3 < nch) {
            MBAR_WAIT(mb + 24 + pstage * 8, pphase);
            issue(c + 3, pstage);
            CP_MBAR_ARRIVE(mb + pstage * 8);
            pstage++; if (pstage == 3) { pstage = 0; pphase ^= 1; }
        }
    }

    // epilogue: mu = silu(acc1) * acc2
    #pragma unroll
    for (int mt = 0; mt < 4; mt++) {
        #pragma unroll
        for (int nt = 0; nt < 4; nt++) {
            int col = colBlock + warp_n * 32 + nt * 8 + (lane & 3) * 2;
            #pragma unroll
            for (int half = 0; half < 2; half++) {
                int row = rowBlock + warp_m * 64 + mt * 16 + (lane >> 2) + half * 8;
                size_t idx = (size_t)row * M + col;
                float g0 = acc1[mt][nt][half * 2 + 0], u0 = acc2[mt][nt][half * 2 + 0];
                float g1 = acc1[mt][nt][half * 2 + 1], u1 = acc2[mt][nt][half * 2 + 1];
                float f0 = g0 * fast_sig(g0) * u0;
                float f1 = g1 * fast_sig(g1) * u1;
                *reinterpret_cast<uint32_t*>(Ch + idx) =
                    pack_h2(__float2half(f0), __float2half(f1));
            }
        }
    }
}

// ---------------------------------------------------------------------------
// Parallel Hawk scan, recompute style
// ---------------------------------------------------------------------------
__global__ __launch_bounds__(256) void scan_part1(
    const f16* __restrict__ xin, const float* __restrict__ a,
    float* __restrict__ csum)
{
    int id = blockIdx.x * 256 + threadIdx.x;
    int chunk = id >> 13;
    int chp = id & (NCHAN - 1);
    int b = chp >> 11;
    int d = chp & (DREC - 1);
    size_t base = ((size_t)b * TLEN + (size_t)chunk * SCHUNK) * DREC + d;

    float h = 0.0f, Aacc = 1.0f;
    #pragma unroll 4
    for (int t = 0; t < SCHUNK; t++) {
        size_t idx = base + (size_t)t * DREC;
        float at = __ldg(&a[idx]);
        float xt = __half2float(__ldg(&xin[idx]));
        float s = sqrtf(fmaf(-at, at, 1.0f) + 1e-8f);
        h = fmaf(at, h, s * xt);
        Aacc *= at;
    }
    csum[(size_t)chunk * NCHAN + chp] = Aacc;
    csum[(size_t)NCHUNKS * NCHAN + (size_t)chunk * NCHAN + chp] = h;
}

__global__ __launch_bounds__(256) void scan_part2(
    const float* __restrict__ csum, float* __restrict__ carry)
{
    int chp = blockIdx.x * 256 + threadIdx.x;
    float h = 0.0f;
    #pragma unroll 8
    for (int c = 0; c < NCHUNKS; c++) {
        carry[(size_t)c * NCHAN + chp] = h;
        float Ac = csum[(size_t)c * NCHAN + chp];
        float hc = csum[(size_t)NCHUNKS * NCHAN + (size_t)c * NCHAN + chp];
        h = fmaf(Ac, h, hc);
    }
}

__global__ __launch_bounds__(256) void scan_part3(
    const f16* __restrict__ xin, const float* __restrict__ a,
    const f16* __restrict__ gate, const float* __restrict__ carry,
    f16* __restrict__ y)
{
    int id = blockIdx.x * 256 + threadIdx.x;
    int chunk = id >> 13;
    int chp = id & (NCHAN - 1);
    int b = chp >> 11;
    int d = chp & (DREC - 1);
    size_t base = ((size_t)b * TLEN + (size_t)chunk * SCHUNK) * DREC + d;

    float h = __ldg(&carry[(size_t)chunk * NCHAN + chp]);
    #pragma unroll 4
    for (int t = 0; t < SCHUNK; t++) {
        size_t idx = base + (size_t)t * DREC;
        float at = __ldg(&a[idx]);
        float xt = __half2float(__ldg(&xin[idx]));
        float gt = __half2float(__ldg(&gate[idx]));
        float s = sqrtf(fmaf(-at, at, 1.0f) + 1e-8f);
        h = fmaf(at, h, s * xt);
        y[idx] = __float2half(gt * h);
    }
}

// ---------------------------------------------------------------------------
// Launch
// ---------------------------------------------------------------------------
#define SYM(p, s) cudaGetSymbolAddress((void**)&p, s)

extern "C" void kernel_launch(void* const* d_in, const int* in_sizes, int n_in,
                              void* d_out, int out_size)
{
    const float* x       = (const float*)d_in[0];
    const float* ln1_w   = (const float*)d_in[1];
    const float* ln2_w   = (const float*)d_in[2];
    const float* w_in    = (const float*)d_in[3];
    const float* w_gate  = (const float*)d_in[4];
    const float* a_param = (const float*)d_in[5];
    const float* w_a     = (const float*)d_in[6];
    const float* w_out   = (const float*)d_in[7];
    const float* w_mg    = (const float*)d_in[8];
    const float* w_mu    = (const float*)d_in[9];
    const float* w_md    = (const float*)d_in[10];
    float* out = (float*)d_out;

    f16 *hh, *h2h, *xinh, *gateh, *yh, *muh;
    float *xres, *aa, *csum, *carry;
    f16 *wi, *wg, *wa, *wo, *wmgp, *wmup, *wmdp;

    SYM(hh, g_h);     SYM(h2h, g_h2);
    SYM(xinh, g_xin); SYM(gateh, g_gate);
    SYM(yh, g_y);     SYM(muh, g_mu);
    SYM(xres, g_xres); SYM(aa, g_a);
    SYM(csum, g_csum); SYM(carry, g_carry);
    SYM(wi, g_wi);  SYM(wg, g_wg);  SYM(wa, g_wa);  SYM(wo, g_wo);
    SYM(wmgp, g_wmg); SYM(wmup, g_wmu); SYM(wmdp, g_wmd);

    cudaFuncSetAttribute(mma_gemm<EPI_NONE, true>,          cudaFuncAttributeMaxDynamicSharedMemorySize, GEMM_SMEM);
    cudaFuncSetAttribute(mma_gemm<EPI_SIGMOID, true>,       cudaFuncAttributeMaxDynamicSharedMemorySize, GEMM_SMEM);
    cudaFuncSetAttribute(mma_gemm<EPI_BIAS_SIGMOID, false>, cudaFuncAttributeMaxDynamicSharedMemorySize, GEMM_SMEM);
    cudaFuncSetAttribute(mma_gemm<EPI_RESADD, false>,       cudaFuncAttributeMaxDynamicSharedMemorySize, GEMM_SMEM);
    cudaFuncSetAttribute(mma_gemm_dual,                     cudaFuncAttributeMaxDynamicSharedMemorySize, GEMM_SMEM);

    dim3 blk(256);
    dim3 gblk(128);
    const int GY = NTOK / 128;   // 128

    const int n_ih = DREC * HIDDEN / 4;   // 524288
    const int n_aa = DREC * DREC / 4;     // 1048576
    const int n_mh = INTER * HIDDEN / 4;  // 1048576

    // launch 0: convert all 7 weights to fp16
    {
        int total = 3 * n_ih + n_aa + 3 * n_mh;
        conv7<<<(total + 255) / 256, blk>>>(
            w_in, wi, n_ih,
            w_gate, wg, n_ih,
            w_a, wa, n_aa,
            w_out, wo, n_ih,
            w_mg, wmgp, n_mh,
            w_mu, wmup, n_mh,
            w_md, wmdp, n_mh);
    }

    // launch 1: h = rmsnorm(x, ln1)
    rmsnorm_h16<<<NTOK, blk>>>(x, ln1_w, hh);

    // launch 2: xin = h @ w_in^T
    mma_gemm<EPI_NONE, true><<<dim3(DREC / 128, GY), gblk, GEMM_SMEM>>>(
        hh, wi, nullptr, xinh, nullptr, DREC, HIDDEN);

    // launch 3: gate = sigmoid(h @ w_gate^T)  (f16)
    mma_gemm<EPI_SIGMOID, true><<<dim3(DREC / 128, GY), gblk, GEMM_SMEM>>>(
        hh, wg, nullptr, gateh, nullptr, DREC, HIDDEN);

    // launch 4: a = sigmoid(a_param + xin @ w_a^T)  (f32)
    mma_gemm<EPI_BIAS_SIGMOID, false><<<dim3(DREC / 128, GY), gblk, GEMM_SMEM>>>(
        xinh, wa, aa, nullptr, a_param, DREC, DREC);

    // launch 5 (ncu profiles this): scan part1
    scan_part1<<<(NCHUNKS * NCHAN) / 256, blk>>>(xinh, aa, csum);
    scan_part2<<<NCHAN / 256, blk>>>(csum, carry);
    scan_part3<<<(NCHUNKS * NCHAN) / 256, blk>>>(xinh, aa, gateh, carry, yh);

    // xres = x + y @ w_out^T
    mma_gemm<EPI_RESADD, false><<<dim3(HIDDEN / 128, GY), gblk, GEMM_SMEM>>>(
        yh, wo, xres, nullptr, x, HIDDEN, DREC);

    // h2 = rmsnorm(xres, ln2)
    rmsnorm_h16<<<NTOK, blk>>>(xres, ln2_w, h2h);

    // fused MLP gate+up: mu = silu(h2@Wg^T) * (h2@Wu^T)
    mma_gemm_dual<<<dim3(INTER / 64, GY), gblk, GEMM_SMEM>>>(
        h2h, wmgp, wmup, muh, INTER, HIDDEN);

    // out = xres + mu @ w_mlp_down^T
    mma_gemm<EPI_RESADD, false><<<dim3(HIDDEN / 128, GY), gblk, GEMM_SMEM>>>(
        muh, wmdp, out, nullptr, xres, HIDDEN, INTER);
}

// round 12
// speedup vs baseline: 3.2515x; 1.0020x over previous
#include <cuda_runtime.h>
#include <cuda_fp16.h>
#include <math.h>
#include <stdint.h>

// ---------------------------------------------------------------------------
// HawkBlock: fp16 mma.sync GEMMs, f32 accum, 3-stage mbarrier ring.
// Dual-B fusions: (w_in + w_gate) and (mlp gate + up -> silu fused).
// Fast-math epilogues, f16 'a', recompute-style parallel scan.
// ---------------------------------------------------------------------------

#define NTOK   16384
#define HIDDEN 1024
#define DREC   2048
#define INTER  4096
#define TLEN   4096
#define NB     4

#define SCHUNK   64
#define NCHUNKS  (TLEN / SCHUNK)   // 64
#define NCHAN    (NB * DREC)       // 8192

typedef __half f16;

// ---- static scratch ----
__device__ f16   g_h   [(size_t)NTOK * HIDDEN];
__device__ f16   g_h2  [(size_t)NTOK * HIDDEN];
__device__ float g_xres[(size_t)NTOK * HIDDEN];
__device__ f16   g_xin [(size_t)NTOK * DREC];
__device__ f16   g_gate[(size_t)NTOK * DREC];
__device__ f16   g_a   [(size_t)NTOK * DREC];
__device__ f16   g_y   [(size_t)NTOK * DREC];
__device__ f16   g_mu  [(size_t)NTOK * INTER];
__device__ float g_csum [2 * NCHUNKS * NCHAN];
__device__ float g_carry[NCHUNKS * NCHAN];

// ---- fp16 weights ----
__device__ f16 g_wi [(size_t)DREC * HIDDEN];
__device__ f16 g_wg [(size_t)DREC * HIDDEN];
__device__ f16 g_wa [(size_t)DREC * DREC];
__device__ f16 g_wo [(size_t)HIDDEN * DREC];
__device__ f16 g_wmg[(size_t)INTER * HIDDEN];
__device__ f16 g_wmu[(size_t)INTER * HIDDEN];
__device__ f16 g_wmd[(size_t)HIDDEN * INTER];

// ---------------------------------------------------------------------------
// helpers
// ---------------------------------------------------------------------------
__device__ __forceinline__ uint32_t smem_u32(const void* p) {
    uint32_t a;
    asm("{ .reg .u64 t; cvta.to.shared.u64 t, %1; cvt.u32.u64 %0, t; }"
        : "=r"(a) : "l"(p));
    return a;
}
__device__ __forceinline__ void cp16(uint32_t dst, const void* src) {
    asm volatile("cp.async.cg.shared.global [%0], [%1], 16;"
                 :: "r"(dst), "l"(src));
}
__device__ __forceinline__ void ldsm4(uint32_t (&r)[4], uint32_t addr) {
    asm volatile("ldmatrix.sync.aligned.m8n8.x4.shared.b16 {%0,%1,%2,%3}, [%4];"
                 : "=r"(r[0]), "=r"(r[1]), "=r"(r[2]), "=r"(r[3]) : "r"(addr));
}
__device__ __forceinline__ void mma_f16(float (&d)[4], const uint32_t (&a)[4],
                                        uint32_t b0, uint32_t b1) {
    asm volatile("mma.sync.aligned.m16n8k16.row.col.f32.f16.f16.f32 "
                 "{%0,%1,%2,%3}, {%4,%5,%6,%7}, {%8,%9}, {%0,%1,%2,%3};"
                 : "+f"(d[0]), "+f"(d[1]), "+f"(d[2]), "+f"(d[3])
                 : "r"(a[0]), "r"(a[1]), "r"(a[2]), "r"(a[3]), "r"(b0), "r"(b1));
}
__device__ __forceinline__ uint32_t pack_h2(f16 a, f16 b) {
    __half2 t = __halves2half2(a, b);
    return *reinterpret_cast<uint32_t*>(&t);
}
__device__ __forceinline__ float fast_sig(float v) {
    return __fdividef(1.0f, 1.0f + __expf(-v));
}

// ---- mbarrier primitives ----
#define MBAR_INIT(addr, cnt) \
    asm volatile("mbarrier.init.shared.b64 [%0], %1;" \
                 :: "r"((uint32_t)(addr)), "r"((uint32_t)(cnt)) : "memory")
#define MBAR_ARRIVE(addr) \
    asm volatile("mbarrier.arrive.shared.b64 _, [%0];" \
                 :: "r"((uint32_t)(addr)) : "memory")
#define CP_MBAR_ARRIVE(addr) \
    asm volatile("cp.async.mbarrier.arrive.noinc.shared.b64 [%0];" \
                 :: "r"((uint32_t)(addr)) : "memory")
#define MBAR_WAIT(addr, parity) do {                                            \
    uint32_t _m = (uint32_t)(addr); uint32_t _p = (uint32_t)(parity);           \
    uint32_t _d;                                                                \
    asm volatile("{\n\t.reg .pred p;\n\t"                                       \
        "mbarrier.try_wait.parity.acquire.cta.shared::cta.b64 p, [%1], %2;\n\t" \
        "selp.b32 %0, 1, 0, p;\n\t}" : "=r"(_d) : "r"(_m), "r"(_p) : "memory"); \
    if (!_d) {                                                                  \
        asm volatile("{\n\t.reg .pred P1;\n\t"                                  \
            "W_%=:\n\t"                                                         \
            "mbarrier.try_wait.parity.acquire.cta.shared::cta.b64 P1, [%0], %1, 0x989680;\n\t" \
            "@P1 bra.uni D_%=;\n\t"                                             \
            "bra.uni W_%=;\n\t"                                                 \
            "D_%=:\n\t}" :: "r"(_m), "r"(_p) : "memory");                       \
    }                                                                           \
} while (0)

// ---------------------------------------------------------------------------
// batched weight convert fp32 -> fp16 (7 arrays, one launch)
// ---------------------------------------------------------------------------
__global__ __launch_bounds__(256) void conv7(
    const float* __restrict__ s0, f16* __restrict__ d0, int n0,
    const float* __restrict__ s1, f16* __restrict__ d1, int n1,
    const float* __restrict__ s2, f16* __restrict__ d2, int n2,
    const float* __restrict__ s3, f16* __restrict__ d3, int n3,
    const float* __restrict__ s4, f16* __restrict__ d4, int n4,
    const float* __restrict__ s5, f16* __restrict__ d5, int n5,
    const float* __restrict__ s6, f16* __restrict__ d6, int n6)
{
    int j = blockIdx.x * 256 + threadIdx.x;
    const float* s; f16* d;
    if (j < n0) { s = s0; d = d0; }
    else { j -= n0;
    if (j < n1) { s = s1; d = d1; }
    else { j -= n1;
    if (j < n2) { s = s2; d = d2; }
    else { j -= n2;
    if (j < n3) { s = s3; d = d3; }
    else { j -= n3;
    if (j < n4) { s = s4; d = d4; }
    else { j -= n4;
    if (j < n5) { s = s5; d = d5; }
    else { j -= n5;
    if (j >= n6) return;
    s = s6; d = d6; }}}}}}
    float4 v = reinterpret_cast<const float4*>(s)[j];
    reinterpret_cast<uint2*>(d)[j] = make_uint2(
        pack_h2(__float2half(v.x), __float2half(v.y)),
        pack_h2(__float2half(v.z), __float2half(v.w)));
}

// ---------------------------------------------------------------------------
// RMSNorm -> fp16
// ---------------------------------------------------------------------------
__global__ __launch_bounds__(256) void rmsnorm_h16(
    const float* __restrict__ x, const float* __restrict__ w,
    f16* __restrict__ o)
{
    int tkn = blockIdx.x;
    int t = threadIdx.x;
    float4 v = reinterpret_cast<const float4*>(x + (size_t)tkn * HIDDEN)[t];
    float s = v.x * v.x + v.y * v.y + v.z * v.z + v.w * v.w;
    #pragma unroll
    for (int o2 = 16; o2 > 0; o2 >>= 1) s += __shfl_xor_sync(0xFFFFFFFFu, s, o2);
    __shared__ float ws[8];
    __shared__ float tot_sh;
    if ((t & 31) == 0) ws[t >> 5] = s;
    __syncthreads();
    if (t < 32) {
        float z = (t < 8) ? ws[t] : 0.0f;
        #pragma unroll
        for (int o2 = 4; o2 > 0; o2 >>= 1) z += __shfl_xor_sync(0xFFFFFFFFu, z, o2);
        if (t == 0) tot_sh = z;
    }
    __syncthreads();
    float r = rsqrtf(tot_sh * (1.0f / HIDDEN) + 1e-6f);
    float4 wv = reinterpret_cast<const float4*>(w)[t];
    size_t q = (size_t)tkn * (HIDDEN / 4) + t;
    reinterpret_cast<uint2*>(o)[q] = make_uint2(
        pack_h2(__float2half(v.x * r * wv.x), __float2half(v.y * r * wv.y)),
        pack_h2(__float2half(v.z * r * wv.z), __float2half(v.w * r * wv.w)));
}

// ---------------------------------------------------------------------------
// Single-B GEMM (CTA 128x128, 4 warps @ 64x64, 3-stage mbarrier ring)
// ---------------------------------------------------------------------------
#define EPI_NONE          0
#define EPI_BIAS_SIGMOID  2
#define EPI_RESADD        3

template<int EPI>
__device__ __forceinline__ float epi_apply(float v,
                                           const float* __restrict__ auxf,
                                           size_t idx, int col)
{
    if (EPI == EPI_BIAS_SIGMOID) return fast_sig(v + __ldg(&auxf[col]));
    if (EPI == EPI_RESADD)       return v + __ldg(&auxf[idx]);
    return v;
}

#define STAGE_B   32768u
#define GEMM_SMEM (3 * 32768 + 64)

template<int EPI, bool OUT16>
__global__ __launch_bounds__(128, 2) void mma_gemm(
    const f16* __restrict__ A, const f16* __restrict__ B,
    float* __restrict__ Cf, f16* __restrict__ Ch,
    const float* __restrict__ auxf, int M, int K)
{
    extern __shared__ char smem[];
    const uint32_t sb = smem_u32(smem);
    const uint32_t mb = sb + 3u * STAGE_B;
    const int tid = threadIdx.x;
    const int lane = tid & 31;
    const int wid = tid >> 5;
    const int warp_m = wid >> 1;
    const int warp_n = wid & 1;
    const int rowBlock = blockIdx.y * 128;
    const int colBlock = blockIdx.x * 128;
    const int nch = K >> 6;

    const f16* gpA = A + (size_t)rowBlock * K;
    const f16* gpB = B + (size_t)colBlock * K;

    if (tid == 0) {
        #pragma unroll
        for (int s = 0; s < 3; s++) {
            MBAR_INIT(mb + s * 8, 128);
            MBAR_INIT(mb + 24 + s * 8, 4);
        }
    }
    __syncthreads();

    auto issue = [&](int c, int buf) {
        const int kb = c * 64;
        uint32_t st = sb + (uint32_t)buf * STAGE_B;
        #pragma unroll
        for (int i = 0; i < 8; i++) {
            int u = tid + i * 128;
            int r = u >> 3, cc = u & 7;
            cp16(st + r * 128 + ((cc ^ (r & 7)) << 4),
                 gpA + (size_t)r * K + kb + cc * 8);
        }
        #pragma unroll
        for (int i = 0; i < 8; i++) {
            int u = tid + i * 128;
            int r = u >> 3, cc = u & 7;
            cp16(st + 16384u + r * 128 + ((cc ^ (r & 7)) << 4),
                 gpB + (size_t)r * K + kb + cc * 8);
        }
    };

    float acc[4][8][4];
    #pragma unroll
    for (int i = 0; i < 4; i++)
        #pragma unroll
        for (int j = 0; j < 8; j++)
            #pragma unroll
            for (int k = 0; k < 4; k++) acc[i][j][k] = 0.0f;

    int pstage = 0, pphase = 1;
    int cstage = 0, cphase = 0;

    #pragma unroll
    for (int s = 0; s < 3; s++) {
        if (s < nch) {
            MBAR_WAIT(mb + 24 + pstage * 8, pphase);
            issue(s, pstage);
            CP_MBAR_ARRIVE(mb + pstage * 8);
            pstage++; if (pstage == 3) { pstage = 0; pphase ^= 1; }
        }
    }

    const int aRow0 = warp_m * 64 + (lane & 7) + ((lane >> 3) & 1) * 8;
    const int aKh   = (lane >> 4) & 1;
    const int bRow0 = warp_n * 64 + ((lane >> 4) & 1) * 8 + (lane & 7);
    const int bKh   = (lane >> 3) & 1;
    const int swz   = lane & 7;

    for (int c = 0; c < nch; c++) {
        int s = cstage;
        MBAR_WAIT(mb + s * 8, cphase);
        cstage++; if (cstage == 3) { cstage = 0; cphase ^= 1; }

        uint32_t st = sb + (uint32_t)s * STAGE_B;
        #pragma unroll
        for (int ks = 0; ks < 4; ks++) {
            uint32_t afr[4][4];
            #pragma unroll
            for (int mt = 0; mt < 4; mt++) {
                uint32_t roff = (uint32_t)(aRow0 + mt * 16) * 128
                              + (uint32_t)(((ks * 2 + aKh) ^ swz) << 4);
                ldsm4(afr[mt], st + roff);
            }
            uint32_t bfr[8][2];
            #pragma unroll
            for (int p = 0; p < 4; p++) {
                uint32_t roff = (uint32_t)(bRow0 + p * 16) * 128
                              + (uint32_t)(((ks * 2 + bKh) ^ swz) << 4);
                uint32_t t4[4];
                ldsm4(t4, st + 16384u + roff);
                bfr[2 * p][0] = t4[0]; bfr[2 * p][1] = t4[1];
                bfr[2 * p + 1][0] = t4[2]; bfr[2 * p + 1][1] = t4[3];
            }
            #pragma unroll
            for (int mt = 0; mt < 4; mt++)
                #pragma unroll
                for (int nt = 0; nt < 8; nt++)
                    mma_f16(acc[mt][nt], afr[mt], bfr[nt][0], bfr[nt][1]);
        }

        if (lane == 0) MBAR_ARRIVE(mb + 24 + s * 8);

        if (c + 3 < nch) {
            MBAR_WAIT(mb + 24 + pstage * 8, pphase);
            issue(c + 3, pstage);
            CP_MBAR_ARRIVE(mb + pstage * 8);
            pstage++; if (pstage == 3) { pstage = 0; pphase ^= 1; }
        }
    }

    #pragma unroll
    for (int mt = 0; mt < 4; mt++) {
        #pragma unroll
        for (int nt = 0; nt < 8; nt++) {
            int col = colBlock + warp_n * 64 + nt * 8 + (lane & 3) * 2;
            #pragma unroll
            for (int half = 0; half < 2; half++) {
                int row = rowBlock + warp_m * 64 + mt * 16 + (lane >> 2) + half * 8;
                size_t idx = (size_t)row * M + col;
                float f0 = epi_apply<EPI>(acc[mt][nt][half * 2 + 0], auxf, idx, col);
                float f1 = epi_apply<EPI>(acc[mt][nt][half * 2 + 1], auxf, idx + 1, col + 1);
                if (OUT16) {
                    *reinterpret_cast<uint32_t*>(Ch + idx) =
                        pack_h2(__float2half(f0), __float2half(f1));
                } else {
                    *reinterpret_cast<float2*>(Cf + idx) = make_float2(f0, f1);
                }
            }
        }
    }
}

// ---------------------------------------------------------------------------
// Dual-B GEMM: computes T1 = A@B1^T and T2 = A@B2^T on one A pass.
// FUSE_SILU=1: one output  C1 = silu(T1)*T2        (MLP gate+up)
// FUSE_SILU=0: two outputs C1 = T1, C2 = sigmoid(T2) (w_in + w_gate)
// CTA 128 rows x 64 cols, 4 warps (64x32 per matrix), 3-stage ring.
// ---------------------------------------------------------------------------
template<int FUSE_SILU>
__global__ __launch_bounds__(128, 2) void mma_gemm_dual(
    const f16* __restrict__ A, const f16* __restrict__ B1,
    const f16* __restrict__ B2, f16* __restrict__ C1, f16* __restrict__ C2,
    int M, int K)
{
    extern __shared__ char smem[];
    const uint32_t sb = smem_u32(smem);
    const uint32_t mb = sb + 3u * STAGE_B;
    const int tid = threadIdx.x;
    const int lane = tid & 31;
    const int wid = tid >> 5;
    const int warp_m = wid >> 1;
    const int warp_n = wid & 1;
    const int rowBlock = blockIdx.y * 128;
    const int colBlock = blockIdx.x * 64;
    const int nch = K >> 6;

    const f16* gpA  = A  + (size_t)rowBlock * K;
    const f16* gpB1 = B1 + (size_t)colBlock * K;
    const f16* gpB2 = B2 + (size_t)colBlock * K;

    if (tid == 0) {
        #pragma unroll
        for (int s = 0; s < 3; s++) {
            MBAR_INIT(mb + s * 8, 128);
            MBAR_INIT(mb + 24 + s * 8, 4);
        }
    }
    __syncthreads();

    auto issue = [&](int c, int buf) {
        const int kb = c * 64;
        uint32_t st = sb + (uint32_t)buf * STAGE_B;
        #pragma unroll
        for (int i = 0; i < 8; i++) {
            int u = tid + i * 128;
            int r = u >> 3, cc = u & 7;
            cp16(st + r * 128 + ((cc ^ (r & 7)) << 4),
                 gpA + (size_t)r * K + kb + cc * 8);
        }
        #pragma unroll
        for (int i = 0; i < 4; i++) {
            int u = tid + i * 128;
            int r = u >> 3, cc = u & 7;
            cp16(st + 16384u + r * 128 + ((cc ^ (r & 7)) << 4),
                 gpB1 + (size_t)r * K + kb + cc * 8);
        }
        #pragma unroll
        for (int i = 0; i < 4; i++) {
            int u = tid + i * 128;
            int r = u >> 3, cc = u & 7;
            cp16(st + 24576u + r * 128 + ((cc ^ (r & 7)) << 4),
                 gpB2 + (size_t)r * K + kb + cc * 8);
        }
    };

    float acc1[4][4][4], acc2[4][4][4];
    #pragma unroll
    for (int i = 0; i < 4; i++)
        #pragma unroll
        for (int j = 0; j < 4; j++)
            #pragma unroll
            for (int k = 0; k < 4; k++) { acc1[i][j][k] = 0.0f; acc2[i][j][k] = 0.0f; }

    int pstage = 0, pphase = 1;
    int cstage = 0, cphase = 0;

    #pragma unroll
    for (int s = 0; s < 3; s++) {
        if (s < nch) {
            MBAR_WAIT(mb + 24 + pstage * 8, pphase);
            issue(s, pstage);
            CP_MBAR_ARRIVE(mb + pstage * 8);
            pstage++; if (pstage == 3) { pstage = 0; pphase ^= 1; }
        }
    }

    const int aRow0 = warp_m * 64 + (lane & 7) + ((lane >> 3) & 1) * 8;
    const int aKh   = (lane >> 4) & 1;
    const int bRow0 = warp_n * 32 + ((lane >> 4) & 1) * 8 + (lane & 7);
    const int bKh   = (lane >> 3) & 1;
    const int swz   = lane & 7;

    for (int c = 0; c < nch; c++) {
        int s = cstage;
        MBAR_WAIT(mb + s * 8, cphase);
        cstage++; if (cstage == 3) { cstage = 0; cphase ^= 1; }

        uint32_t st = sb + (uint32_t)s * STAGE_B;
        #pragma unroll
        for (int ks = 0; ks < 4; ks++) {
            uint32_t afr[4][4];
            #pragma unroll
            for (int mt = 0; mt < 4; mt++) {
                uint32_t roff = (uint32_t)(aRow0 + mt * 16) * 128
                              + (uint32_t)(((ks * 2 + aKh) ^ swz) << 4);
                ldsm4(afr[mt], st + roff);
            }
            uint32_t b1fr[4][2], b2fr[4][2];
            #pragma unroll
            for (int p = 0; p < 2; p++) {
                uint32_t roff = (uint32_t)(bRow0 + p * 16) * 128
                              + (uint32_t)(((ks * 2 + bKh) ^ swz) << 4);
                uint32_t t4[4];
                ldsm4(t4, st + 16384u + roff);
                b1fr[2 * p][0] = t4[0]; b1fr[2 * p][1] = t4[1];
                b1fr[2 * p + 1][0] = t4[2]; b1fr[2 * p + 1][1] = t4[3];
                ldsm4(t4, st + 24576u + roff);
                b2fr[2 * p][0] = t4[0]; b2fr[2 * p][1] = t4[1];
                b2fr[2 * p + 1][0] = t4[2]; b2fr[2 * p + 1][1] = t4[3];
            }
            #pragma unroll
            for (int mt = 0; mt < 4; mt++)
                #pragma unroll
                for (int nt = 0; nt < 4; nt++)
                    mma_f16(acc1[mt][nt], afr[mt], b1fr[nt][0], b1fr[nt][1]);
            #pragma unroll
            for (int mt = 0; mt < 4; mt++)
                #pragma unroll
                for (int nt = 0; nt < 4; nt++)
                    mma_f16(acc2[mt][nt], afr[mt], b2fr[nt][0], b2fr[nt][1]);
        }

        if (lane == 0) MBAR_ARRIVE(mb + 24 + s * 8);

        if (c + 3 < nch) {
            MBAR_WAIT(mb + 24 + pstage * 8, pphase);
            issue(c + 3, pstage);
            CP_MBAR_ARRIVE(mb + pstage * 8);
            pstage++; if (pstage == 3) { pstage = 0; pphase ^= 1; }
        }
    }

    #pragma unroll
    for (int mt = 0; mt < 4; mt++) {
        #pragma unroll
        for (int nt = 0; nt < 4; nt++) {
            int col = colBlock + warp_n * 32 + nt * 8 + (lane & 3) * 2;
            #pragma unroll
            for (int half = 0; half < 2; half++) {
                int row = rowBlock + warp_m * 64 + mt * 16 + (lane >> 2) + half * 8;
                size_t idx = (size_t)row * M + col;
                float t10 = acc1[mt][nt][half * 2 + 0], t20 = acc2[mt][nt][half * 2 + 0];
                float t11 = acc1[mt][nt][half * 2 + 1], t21 = acc2[mt][nt][half * 2 + 1];
                if (FUSE_SILU) {
                    float f0 = t10 * fast_sig(t10) * t20;
                    float f1 = t11 * fast_sig(t11) * t21;
                    *reinterpret_cast<uint32_t*>(C1 + idx) =
                        pack_h2(__float2half(f0), __float2half(f1));
                } else {
                    *reinterpret_cast<uint32_t*>(C1 + idx) =
                        pack_h2(__float2half(t10), __float2half(t11));
                    *reinterpret_cast<uint32_t*>(C2 + idx) =
                        pack_h2(__float2half(fast_sig(t20)), __float2half(fast_sig(t21)));
                }
            }
        }
    }
}

// ---------------------------------------------------------------------------
// Parallel Hawk scan, recompute style ('a' is f16)
// ---------------------------------------------------------------------------
__global__ __launch_bounds__(256) void scan_part1(
    const f16* __restrict__ xin, const f16* __restrict__ a,
    float* __restrict__ csum)
{
    int id = blockIdx.x * 256 + threadIdx.x;
    int chunk = id >> 13;
    int chp = id & (NCHAN - 1);
    int b = chp >> 11;
    int d = chp & (DREC - 1);
    size_t base = ((size_t)b * TLEN + (size_t)chunk * SCHUNK) * DREC + d;

    float h = 0.0f, Aacc = 1.0f;
    #pragma unroll 4
    for (int t = 0; t < SCHUNK; t++) {
        size_t idx = base + (size_t)t * DREC;
        float at = __half2float(__ldg(&a[idx]));
        float xt = __half2float(__ldg(&xin[idx]));
        float s = sqrtf(fmaf(-at, at, 1.0f) + 1e-8f);
        h = fmaf(at, h, s * xt);
        Aacc *= at;
    }
    csum[(size_t)chunk * NCHAN + chp] = Aacc;
    csum[(size_t)NCHUNKS * NCHAN + (size_t)chunk * NCHAN + chp] = h;
}

__global__ __launch_bounds__(256) void scan_part2(
    const float* __restrict__ csum, float* __restrict__ carry)
{
    int chp = blockIdx.x * 256 + threadIdx.x;
    float h = 0.0f;
    #pragma unroll 8
    for (int c = 0; c < NCHUNKS; c++) {
        carry[(size_t)c * NCHAN + chp] = h;
        float Ac = csum[(size_t)c * NCHAN + chp];
        float hc = csum[(size_t)NCHUNKS * NCHAN + (size_t)c * NCHAN + chp];
        h = fmaf(Ac, h, hc);
    }
}

__global__ __launch_bounds__(256) void scan_part3(
    const f16* __restrict__ xin, const f16* __restrict__ a,
    const f16* __restrict__ gate, const float* __restrict__ carry,
    f16* __restrict__ y)
{
    int id = blockIdx.x * 256 + threadIdx.x;
    int chunk = id >> 13;
    int chp = id & (NCHAN - 1);
    int b = chp >> 11;
    int d = chp & (DREC - 1);
    size_t base = ((size_t)b * TLEN + (size_t)chunk * SCHUNK) * DREC + d;

    float h = __ldg(&carry[(size_t)chunk * NCHAN + chp]);
    #pragma unroll 4
    for (int t = 0; t < SCHUNK; t++) {
        size_t idx = base + (size_t)t * DREC;
        float at = __half2float(__ldg(&a[idx]));
        float xt = __half2float(__ldg(&xin[idx]));
        float gt = __half2float(__ldg(&gate[idx]));
        float s = sqrtf(fmaf(-at, at, 1.0f) + 1e-8f);
        h = fmaf(at, h, s * xt);
        y[idx] = __float2half(gt * h);
    }
}

// ---------------------------------------------------------------------------
// Launch
// ---------------------------------------------------------------------------
#define SYM(p, s) cudaGetSymbolAddress((void**)&p, s)

extern "C" void kernel_launch(void* const* d_in, const int* in_sizes, int n_in,
                              void* d_out, int out_size)
{
    const float* x       = (const float*)d_in[0];
    const float* ln1_w   = (const float*)d_in[1];
    const float* ln2_w   = (const float*)d_in[2];
    const float* w_in    = (const float*)d_in[3];
    const float* w_gate  = (const float*)d_in[4];
    const float* a_param = (const float*)d_in[5];
    const float* w_a     = (const float*)d_in[6];
    const float* w_out   = (const float*)d_in[7];
    const float* w_mg    = (const float*)d_in[8];
    const float* w_mu    = (const float*)d_in[9];
    const float* w_md    = (const float*)d_in[10];
    float* out = (float*)d_out;

    f16 *hh, *h2h, *xinh, *gateh, *ah, *yh, *muh;
    float *xres, *csum, *carry;
    f16 *wi, *wg, *wa, *wo, *wmgp, *wmup, *wmdp;

    SYM(hh, g_h);     SYM(h2h, g_h2);
    SYM(xinh, g_xin); SYM(gateh, g_gate); SYM(ah, g_a);
    SYM(yh, g_y);     SYM(muh, g_mu);
    SYM(xres, g_xres);
    SYM(csum, g_csum); SYM(carry, g_carry);
    SYM(wi, g_wi);  SYM(wg, g_wg);  SYM(wa, g_wa);  SYM(wo, g_wo);
    SYM(wmgp, g_wmg); SYM(wmup, g_wmu); SYM(wmdp, g_wmd);

    cudaFuncSetAttribute(mma_gemm<EPI_NONE, true>,          cudaFuncAttributeMaxDynamicSharedMemorySize, GEMM_SMEM);
    cudaFuncSetAttribute(mma_gemm<EPI_BIAS_SIGMOID, true>,  cudaFuncAttributeMaxDynamicSharedMemorySize, GEMM_SMEM);
    cudaFuncSetAttribute(mma_gemm<EPI_RESADD, false>,       cudaFuncAttributeMaxDynamicSharedMemorySize, GEMM_SMEM);
    cudaFuncSetAttribute(mma_gemm_dual<0>,                  cudaFuncAttributeMaxDynamicSharedMemorySize, GEMM_SMEM);
    cudaFuncSetAttribute(mma_gemm_dual<1>,                  cudaFuncAttributeMaxDynamicSharedMemorySize, GEMM_SMEM);

    dim3 blk(256);
    dim3 gblk(128);
    const int GY = NTOK / 128;   // 128

    const int n_ih = DREC * HIDDEN / 4;   // 524288
    const int n_aa = DREC * DREC / 4;     // 1048576
    const int n_mh = INTER * HIDDEN / 4;  // 1048576

    // launch 0: convert all 7 weights to fp16
    {
        int total = 3 * n_ih + n_aa + 3 * n_mh;
        conv7<<<(total + 255) / 256, blk>>>(
            w_in, wi, n_ih,
            w_gate, wg, n_ih,
            w_a, wa, n_aa,
            w_out, wo, n_ih,
            w_mg, wmgp, n_mh,
            w_mu, wmup, n_mh,
            w_md, wmdp, n_mh);
    }

    // launch 1: h = rmsnorm(x, ln1)
    rmsnorm_h16<<<NTOK, blk>>>(x, ln1_w, hh);

    // launch 2: fused xin = h@Wi^T, gate = sigmoid(h@Wg^T)
    mma_gemm_dual<0><<<dim3(DREC / 64, GY), gblk, GEMM_SMEM>>>(
        hh, wi, wg, xinh, gateh, DREC, HIDDEN);

    // launch 3: a = sigmoid(a_param + xin @ w_a^T)  (f16)
    mma_gemm<EPI_BIAS_SIGMOID, true><<<dim3(DREC / 128, GY), gblk, GEMM_SMEM>>>(
        xinh, wa, nullptr, ah, a_param, DREC, DREC);

    // scan
    scan_part1<<<(NCHUNKS * NCHAN) / 256, blk>>>(xinh, ah, csum);
    scan_part2<<<NCHAN / 256, blk>>>(csum, carry);
    scan_part3<<<(NCHUNKS * NCHAN) / 256, blk>>>(xinh, ah, gateh, carry, yh);

    // xres = x + y @ w_out^T
    mma_gemm<EPI_RESADD, false><<<dim3(HIDDEN / 128, GY), gblk, GEMM_SMEM>>>(
        yh, wo, xres, nullptr, x, HIDDEN, DREC);

    // h2 = rmsnorm(xres, ln2)
    rmsnorm_h16<<<NTOK, blk>>>(xres, ln2_w, h2h);

    // fused MLP gate+up: mu = silu(h2@Wg^T) * (h2@Wu^T)
    mma_gemm_dual<1><<<dim3(INTER / 64, GY), gblk, GEMM_SMEM>>>(
        h2h, wmgp, wmup, muh, nullptr, INTER, HIDDEN);

    // out = xres + mu @ w_mlp_down^T
    mma_gemm<EPI_RESADD, false><<<dim3(HIDDEN / 128, GY), gblk, GEMM_SMEM>>>(
        muh, wmdp, out, nullptr, xres, HIDDEN, INTER);
}